// round 8
// baseline (speedup 1.0000x reference)
#include <cuda_runtime.h>
#include <cuda_bf16.h>
#include <cstdint>

#define Bsz 512
#define Cc  271
#define Tt  281
#define Hh  128
#define NCLS 1854
#define BT  (Bsz*Tt)      /* 143872 */
#define G4  512
#define KP0 272           /* padded K for layer0 (multiple of 16) */

typedef unsigned long long u64;
typedef unsigned int u32;

union F4 { float4 v; float f[4]; u64 d[2]; };

__device__ __forceinline__ u64 ffma2(u64 a, u64 b, u64 c){
    u64 d; asm("fma.rn.f32x2 %0, %1, %2, %3;" : "=l"(d) : "l"(a), "l"(b), "l"(c)); return d;
}
__device__ __forceinline__ float2 unpack2(u64 d){
    float lo, hi; asm("mov.b64 {%0, %1}, %2;" : "=f"(lo), "=f"(hi) : "l"(d));
    return make_float2(lo, hi);
}
__device__ __forceinline__ float sigf(float x){ return __fdividef(1.f, 1.f + __expf(-x)); }
__device__ __forceinline__ float tanh_(float x){ return 1.f - __fdividef(2.f, __expf(2.f*x) + 1.f); }

// ------------- device scratch -------------
__device__ float g_xT [(size_t)BT*Cc];
__device__ float g_xwF[(size_t)BT*G4];
__device__ float g_xwB[(size_t)BT*G4];
__device__ float g_h0 [(size_t)BT*2*Hh];
__device__ float g_h1 [(size_t)BT*2*Hh];
__device__ float g_wT [4*Hh*G4];          // 4x [128][512] gate-interleaved W_hh^T
__device__ float g_wih0[2*G4*Cc];
__device__ float g_wih1[2*G4*2*Hh];
__device__ float g_bsum[4*G4];
__device__ float g_att[Bsz*2*Hh];
// bf16 split buffers
__device__ __nv_bfloat16 g_ahi[(size_t)BT*KP0];
__device__ __nv_bfloat16 g_alo[(size_t)BT*KP0];
#define WOFF0F 0
#define WOFF0B (512*KP0)
#define WOFF1F (2*512*KP0)
#define WOFF1B (2*512*KP0 + 512*256)
#define WOFFATT (2*512*KP0 + 2*512*256)
#define WTOT (WOFFATT + 256*256)
__device__ __nv_bfloat16 g_whi[WTOT];
__device__ __nv_bfloat16 g_wlo[WTOT];

__device__ __forceinline__ int oldrow(int n){ return (n&3)*128 + (n>>2); }

// ------------- prep kernels -------------
__global__ void reorder_wih(const float* __restrict__ src, float* __restrict__ dst, int K){
    int i = blockIdx.x*256 + threadIdx.x;
    if (i >= G4*K) return;
    int n = i / K, k = i % K;
    dst[i] = src[oldrow(n)*K + k];
}
__global__ void reorder_whh(const float* __restrict__ src, float* __restrict__ dst){
    int i = blockIdx.x*256 + threadIdx.x;
    if (i >= Hh*G4) return;
    int k = i >> 9, n = i & 511;
    dst[i] = src[oldrow(n)*Hh + k];
}
__global__ void fold_b(const float* __restrict__ bi, const float* __restrict__ bh, float* __restrict__ dst){
    int n = blockIdx.x*256 + threadIdx.x;
    if (n >= G4) return;
    int o = oldrow(n);
    dst[n] = bi[o] + bh[o];
}

// ------------- fp32 -> bf16 hi/lo split (with K padding) -------------
__global__ void conv_split(const float* __restrict__ src, __nv_bfloat16* __restrict__ hi,
                           __nv_bfloat16* __restrict__ lo, size_t total, int Ks, int Kp){
    size_t i = (size_t)blockIdx.x*256 + threadIdx.x;
    if (i >= total) return;
    size_t r = i / Kp; int k = (int)(i - r*Kp);
    float v = (k < Ks) ? src[r*Ks + k] : 0.f;
    __nv_bfloat16 h = __float2bfloat16(v);
    hi[i] = h;
    lo[i] = __float2bfloat16(v - __bfloat162float(h));
}
__global__ void conv_splitT(const float* __restrict__ src, __nv_bfloat16* __restrict__ hi,
                            __nv_bfloat16* __restrict__ lo, int N, int Ks, int Kp){
    int i = blockIdx.x*256 + threadIdx.x;
    if (i >= N*Kp) return;
    int n = i / Kp, k = i % Kp;
    float v = (k < Ks) ? src[(size_t)k*N + n] : 0.f;
    __nv_bfloat16 h = __float2bfloat16(v);
    hi[i] = h;
    lo[i] = __float2bfloat16(v - __bfloat162float(h));
}

// ------------- transpose X[B,C,T] -> xT[B,T,C] -------------
__global__ void transposeX(const float* __restrict__ X, float* __restrict__ xT){
    __shared__ float tile[32][33];
    int b = blockIdx.z;
    int t0 = blockIdx.x*32, c0 = blockIdx.y*32;
    int tx = threadIdx.x, ty = threadIdx.y;
    const float* Xb = X + (size_t)b*Cc*Tt;
    float* xTb = xT + (size_t)b*Tt*Cc;
    #pragma unroll
    for (int i=0;i<32;i+=8){
        int c = c0+ty+i, t = t0+tx;
        if (c<Cc && t<Tt) tile[ty+i][tx] = Xb[(size_t)c*Tt + t];
    }
    __syncthreads();
    #pragma unroll
    for (int i=0;i<32;i+=8){
        int t = t0+ty+i, c = c0+tx;
        if (t<Tt && c<Cc) xTb[(size_t)t*Cc + c] = tile[tx][ty+i];
    }
}

// ------------- tensor-core GEMM with split-bf16 (3 passes = fp32 accuracy) -------
// C[M,N] = act(A[M,K] @ W[N,K]^T + bias).  M,N multiples of 128. Kp multiple of 16.
#define SST 24   /* smem row stride in halves */
__device__ __forceinline__ u32 smaddr(const void* p){ return (u32)__cvta_generic_to_shared(p); }
__device__ __forceinline__ void cpasync16(u32 s, const void* g){
    asm volatile("cp.async.cg.shared.global [%0], [%1], 16;" :: "r"(s), "l"(g));
}
__device__ __forceinline__ void ldsm4(u32* r, u32 a){
    asm volatile("ldmatrix.sync.aligned.m8n8.x4.shared.b16 {%0,%1,%2,%3}, [%4];"
        : "=r"(r[0]),"=r"(r[1]),"=r"(r[2]),"=r"(r[3]) : "r"(a));
}
__device__ __forceinline__ void mma16816(float* d, const u32* a, u32 b0, u32 b1){
    asm volatile("mma.sync.aligned.m16n8k16.row.col.f32.bf16.bf16.f32 "
        "{%0,%1,%2,%3}, {%4,%5,%6,%7}, {%8,%9}, {%0,%1,%2,%3};"
        : "+f"(d[0]),"+f"(d[1]),"+f"(d[2]),"+f"(d[3])
        : "r"(a[0]),"r"(a[1]),"r"(a[2]),"r"(a[3]), "r"(b0),"r"(b1));
}

__global__ __launch_bounds__(256,2)
void mma_gemm(const __nv_bfloat16* __restrict__ Ahi, const __nv_bfloat16* __restrict__ Alo,
              const __nv_bfloat16* __restrict__ Whi, const __nv_bfloat16* __restrict__ Wlo,
              const float* __restrict__ bias, float* __restrict__ C,
              int M, int N, int Kp, int act)
{
    __shared__ __align__(16) __nv_bfloat16 sm[2][4][128*SST];
    int tid = threadIdx.x;
    int wid = tid>>5, lane = tid&31;
    int m0 = blockIdx.y*128, n0 = blockIdx.x*128;
    int wm = (wid>>2)*64, wn = (wid&3)*32;

    float acc[4][4][4];
    #pragma unroll
    for (int i=0;i<4;i++)
      #pragma unroll
      for (int j=0;j<4;j++)
        #pragma unroll
        for (int q=0;q<4;q++) acc[i][j][q] = 0.f;

    const __nv_bfloat16* gsrc[4];
    gsrc[0] = Ahi + (size_t)m0*Kp;
    gsrc[1] = Alo + (size_t)m0*Kp;
    gsrc[2] = Whi + (size_t)n0*Kp;
    gsrc[3] = Wlo + (size_t)n0*Kp;

    int row = tid>>1, half = tid&1;
    int NC = Kp >> 4;

    {   // prologue load chunk 0 -> stage 0
        #pragma unroll
        for (int t=0;t<4;t++){
            const __nv_bfloat16* g = gsrc[t] + (size_t)row*Kp + half*8;
            cpasync16(smaddr(&sm[0][t][row*SST + half*8]), g);
        }
        asm volatile("cp.async.commit_group;" ::: "memory");
    }

    int ar = lane & 15;
    int ac = (lane >> 4) * 8;
    int brn = (lane & 7) + ((lane & 16) ? 8 : 0);
    int bc  = (lane & 8) ? 8 : 0;

    for (int c=0;c<NC;c++){
        if (c+1 < NC){
            int k0 = (c+1)*16, s = (c+1)&1;
            #pragma unroll
            for (int t=0;t<4;t++){
                const __nv_bfloat16* g = gsrc[t] + (size_t)row*Kp + k0 + half*8;
                cpasync16(smaddr(&sm[s][t][row*SST + half*8]), g);
            }
            asm volatile("cp.async.commit_group;" ::: "memory");
            asm volatile("cp.async.wait_group 1;" ::: "memory");
        } else {
            asm volatile("cp.async.wait_group 0;" ::: "memory");
        }
        __syncthreads();
        int s = c & 1;
        const __nv_bfloat16* tA_hi = sm[s][0];
        const __nv_bfloat16* tA_lo = sm[s][1];
        const __nv_bfloat16* tW_hi = sm[s][2];
        const __nv_bfloat16* tW_lo = sm[s][3];

        u32 Af[4][4], Whf[2][4], Wlf[2][4];
        #pragma unroll
        for (int mi=0;mi<4;mi++)
            ldsm4(Af[mi], smaddr(&tA_hi[(wm + mi*16 + ar)*SST + ac]));
        #pragma unroll
        for (int g=0;g<2;g++)
            ldsm4(Whf[g], smaddr(&tW_hi[(wn + g*16 + brn)*SST + bc]));
        // pass 1: Ahi * Whi
        #pragma unroll
        for (int mi=0;mi<4;mi++)
            #pragma unroll
            for (int ni=0;ni<4;ni++)
                mma16816(acc[mi][ni], Af[mi], Whf[ni>>1][(ni&1)*2], Whf[ni>>1][(ni&1)*2+1]);
        // pass 2: Ahi * Wlo
        #pragma unroll
        for (int g=0;g<2;g++)
            ldsm4(Wlf[g], smaddr(&tW_lo[(wn + g*16 + brn)*SST + bc]));
        #pragma unroll
        for (int mi=0;mi<4;mi++)
            #pragma unroll
            for (int ni=0;ni<4;ni++)
                mma16816(acc[mi][ni], Af[mi], Wlf[ni>>1][(ni&1)*2], Wlf[ni>>1][(ni&1)*2+1]);
        // pass 3: Alo * Whi
        #pragma unroll
        for (int mi=0;mi<4;mi++)
            ldsm4(Af[mi], smaddr(&tA_lo[(wm + mi*16 + ar)*SST + ac]));
        #pragma unroll
        for (int mi=0;mi<4;mi++)
            #pragma unroll
            for (int ni=0;ni<4;ni++)
                mma16816(acc[mi][ni], Af[mi], Whf[ni>>1][(ni&1)*2], Whf[ni>>1][(ni&1)*2+1]);
        __syncthreads();
    }

    // epilogue
    int er = lane>>2, ec = (lane&3)*2;
    #pragma unroll
    for (int mi=0;mi<4;mi++){
        #pragma unroll
        for (int ni=0;ni<4;ni++){
            int gm = m0 + wm + mi*16 + er;
            int gn = n0 + wn + ni*8 + ec;
            float b0 = bias ? bias[gn]   : 0.f;
            float b1 = bias ? bias[gn+1] : 0.f;
            float v0 = acc[mi][ni][0] + b0;
            float v1 = acc[mi][ni][1] + b1;
            float v2 = acc[mi][ni][2] + b0;
            float v3 = acc[mi][ni][3] + b1;
            if (act){ v0 = tanh_(v0); v1 = tanh_(v1); v2 = tanh_(v2); v3 = tanh_(v3); }
            *(float2*)&C[(size_t)gm*N + gn]     = make_float2(v0, v1);
            *(float2*)&C[(size_t)(gm+8)*N + gn] = make_float2(v2, v3);
        }
    }
}

// ------------- fp32 GEMM (head only) -------------
__global__ __launch_bounds__(256,2)
void gemm128(const float* __restrict__ A, const float* __restrict__ B,
             const float* __restrict__ bias, float* __restrict__ C,
             int M, int N, int K, int transB, int act)
{
    __shared__ float As2[16][264];
    __shared__ float Bs[16][132];
    int row0 = blockIdx.y*128, col0 = blockIdx.x*128;
    int tid = threadIdx.x;
    int tm = tid >> 4, tn = tid & 15;
    u64 acc[8][4];
    #pragma unroll
    for (int i=0;i<8;i++)
        #pragma unroll
        for (int j=0;j<4;j++) acc[i][j] = 0ull;

    for (int k0=0;k0<K;k0+=16){
        #pragma unroll
        for (int i=0;i<8;i++){
            int idx = tid + i*256;
            int r = idx >> 4, kk = idx & 15;
            int gr = row0+r, gk = k0+kk;
            float v = (gr<M && gk<K) ? A[(size_t)gr*K + gk] : 0.f;
            *(float2*)&As2[kk][2*r] = make_float2(v, v);
        }
        if (transB){
            #pragma unroll
            for (int i=0;i<8;i++){
                int idx = tid + i*256;
                int nn = idx >> 4, kk = idx & 15;
                int gk = k0+kk, gn = col0+nn;
                Bs[kk][nn] = (gk<K && gn<N) ? B[(size_t)gn*K+gk] : 0.f;
            }
        } else {
            #pragma unroll
            for (int i=0;i<8;i++){
                int idx = tid + i*256;
                int nn = idx & 127, kk = idx >> 7;
                int gk = k0+kk, gn = col0+nn;
                Bs[kk][nn] = (gk<K && gn<N) ? B[(size_t)gk*N+gn] : 0.f;
            }
        }
        __syncthreads();
        #pragma unroll
        for (int kk=0;kk<16;kk++){
            F4 b0, b1, a0, a1, a2, a3;
            b0.v = *(const float4*)&Bs[kk][tn*8];
            b1.v = *(const float4*)&Bs[kk][tn*8+4];
            a0.v = *(const float4*)&As2[kk][tm*16];
            a1.v = *(const float4*)&As2[kk][tm*16+4];
            a2.v = *(const float4*)&As2[kk][tm*16+8];
            a3.v = *(const float4*)&As2[kk][tm*16+12];
            u64 bd[4] = { b0.d[0], b0.d[1], b1.d[0], b1.d[1] };
            u64 ad[8] = { a0.d[0], a0.d[1], a1.d[0], a1.d[1],
                          a2.d[0], a2.d[1], a3.d[0], a3.d[1] };
            #pragma unroll
            for (int i=0;i<8;i++)
                #pragma unroll
                for (int j=0;j<4;j++)
                    acc[i][j] = ffma2(ad[i], bd[j], acc[i][j]);
        }
        __syncthreads();
    }
    #pragma unroll
    for (int i=0;i<8;i++){
        int gr = row0 + tm*8 + i;
        if (gr >= M) continue;
        #pragma unroll
        for (int j=0;j<4;j++){
            float2 v = unpack2(acc[i][j]);
            int gn = col0 + tn*8 + j*2;
            if (gn < N){
                float x = v.x + (bias ? bias[gn] : 0.f);
                if (act) x = tanh_(x);
                C[(size_t)gr*N + gn] = x;
            }
            if (gn+1 < N){
                float y = v.y + (bias ? bias[gn+1] : 0.f);
                if (act) y = tanh_(y);
                C[(size_t)gr*N + gn+1] = y;
            }
        }
    }
}

// ------------- LSTM scan (prefetch + double-buffered h) -------------
#define HS 20
#define SCAN_SMEM ((64*G4 + 2*128*HS)*4)

__global__ __launch_bounds__(256,1)
void scan_kernel(const float* __restrict__ xwFp, const float* __restrict__ xwBp,
                 const float* __restrict__ wTF, const float* __restrict__ wTB,
                 float* __restrict__ hout)
{
    extern __shared__ float sm[];
    float* Ws  = sm;
    float* hsA = sm + 64*G4;
    float* hsB = hsA + 128*HS;
    int tid = threadIdx.x;
    int dir = blockIdx.x >> 6;
    int grp = blockIdx.x & 63;
    int b0 = grp*8;
    const float* xw = dir ? xwBp : xwFp;
    const float* wD = dir ? wTB : wTF;
    int hOff = dir*128;
    int h  = tid & 127;
    int rg = tid >> 7;

    for (int i=tid;i<64*G4;i+=256) Ws[i] = wD[i];
    for (int i=tid;i<2*128*HS;i+=256) hsA[i] = 0.f;
    float cst[4] = {0.f,0.f,0.f,0.f};

    const float* xp[4];
    float* hop[4];
    #pragma unroll
    for (int r=0;r<4;r++){
        xp[r]  = xw   + ((size_t)(b0+4*rg+r)*Tt)*G4 + 4*h;
        hop[r] = hout + ((size_t)(b0+4*rg+r)*Tt)*256 + hOff + h;
    }
    __syncthreads();

    int t0 = dir ? (Tt-1) : 0;
    F4 xvc[4];
    #pragma unroll
    for (int r=0;r<4;r++) xvc[r].v = *(const float4*)&xp[r][(size_t)t0*G4];

    for (int s=0;s<Tt;s++){
        int t = dir ? (Tt-1-s) : s;
        float* hsR = (s&1) ? hsB : hsA;
        float* hsW = (s&1) ? hsA : hsB;

        F4 xvn[4];
        if (s+1 < Tt){
            int tn_ = dir ? (Tt-2-s) : (s+1);
            #pragma unroll
            for (int r=0;r<4;r++) xvn[r].v = *(const float4*)&xp[r][(size_t)tn_*G4];
        }

        u64 aIF[4] = {0,0,0,0}, aGO[4] = {0,0,0,0};
        #pragma unroll 8
        for (int k=0;k<64;k++){
            F4 w;  w.v  = *(const float4*)&Ws[k*G4 + 4*h];
            F4 p0; p0.v = *(const float4*)&hsR[k*HS + 8*rg];
            F4 p1; p1.v = *(const float4*)&hsR[k*HS + 8*rg + 4];
            aIF[0]=ffma2(p0.d[0], w.d[0], aIF[0]); aGO[0]=ffma2(p0.d[0], w.d[1], aGO[0]);
            aIF[1]=ffma2(p0.d[1], w.d[0], aIF[1]); aGO[1]=ffma2(p0.d[1], w.d[1], aGO[1]);
            aIF[2]=ffma2(p1.d[0], w.d[0], aIF[2]); aGO[2]=ffma2(p1.d[0], w.d[1], aGO[2]);
            aIF[3]=ffma2(p1.d[1], w.d[0], aIF[3]); aGO[3]=ffma2(p1.d[1], w.d[1], aGO[3]);
        }
        for (int kb=64;kb<128;kb+=8){
            F4 w[8];
            #pragma unroll
            for (int j=0;j<8;j++) w[j].v = *(const float4*)&wD[(size_t)(kb+j)*G4 + 4*h];
            #pragma unroll
            for (int j=0;j<8;j++){
                int k = kb+j;
                F4 p0; p0.v = *(const float4*)&hsR[k*HS + 8*rg];
                F4 p1; p1.v = *(const float4*)&hsR[k*HS + 8*rg + 4];
                aIF[0]=ffma2(p0.d[0], w[j].d[0], aIF[0]); aGO[0]=ffma2(p0.d[0], w[j].d[1], aGO[0]);
                aIF[1]=ffma2(p0.d[1], w[j].d[0], aIF[1]); aGO[1]=ffma2(p0.d[1], w[j].d[1], aGO[1]);
                aIF[2]=ffma2(p1.d[0], w[j].d[0], aIF[2]); aGO[2]=ffma2(p1.d[0], w[j].d[1], aGO[2]);
                aIF[3]=ffma2(p1.d[1], w[j].d[0], aIF[3]); aGO[3]=ffma2(p1.d[1], w[j].d[1], aGO[3]);
            }
        }
        float hnew[4];
        #pragma unroll
        for (int r=0;r<4;r++){
            float2 v1 = unpack2(aIF[r]);
            float2 v2 = unpack2(aGO[r]);
            float gi = v1.x + xvc[r].f[0];
            float gf = v1.y + xvc[r].f[1];
            float gg = v2.x + xvc[r].f[2];
            float go = v2.y + xvc[r].f[3];
            float cc = sigf(gf)*cst[r] + sigf(gi)*tanh_(gg);
            cst[r] = cc;
            hnew[r] = sigf(go)*tanh_(cc);
        }
        #pragma unroll
        for (int r=0;r<4;r++){
            *(float2*)&hsW[h*HS + 2*(4*rg+r)] = make_float2(hnew[r], hnew[r]);
            hop[r][(size_t)t*256] = hnew[r];
        }
        __syncthreads();
        #pragma unroll
        for (int r=0;r<4;r++) xvc[r] = xvn[r];
    }
}

// ------------- attention -------------
__global__ __launch_bounds__(256,1)
void att_kernel(const float* __restrict__ u, const float* __restrict__ h1,
                const float* __restrict__ v, float* __restrict__ att)
{
    __shared__ float sa[Tt];
    __shared__ float red[256];
    int b = blockIdx.x, tid = threadIdx.x;
    for (int t = tid; t < Tt; t += 256){
        const float* ur = u + ((size_t)b*Tt + t)*256;
        float s = 0.f;
        #pragma unroll 8
        for (int k=0;k<256;k++) s += ur[k]*v[k];
        sa[t] = s;
    }
    __syncthreads();
    float m = -3.4e38f;
    for (int t=tid;t<Tt;t+=256) m = fmaxf(m, sa[t]);
    red[tid] = m; __syncthreads();
    for (int off=128; off>0; off>>=1){ if (tid<off) red[tid]=fmaxf(red[tid],red[tid+off]); __syncthreads(); }
    float mx = red[0]; __syncthreads();
    float sum = 0.f;
    for (int t=tid;t<Tt;t+=256){ float e = __expf(sa[t]-mx); sa[t]=e; sum+=e; }
    red[tid] = sum; __syncthreads();
    for (int off=128; off>0; off>>=1){ if (tid<off) red[tid]+=red[tid+off]; __syncthreads(); }
    float inv = __fdividef(1.f, red[0]);
    __syncthreads();
    float acc = 0.f;
    const float* hb = h1 + (size_t)b*Tt*256 + tid;
    #pragma unroll 4
    for (int t=0;t<Tt;t++) acc += hb[(size_t)t*256] * sa[t];
    att[b*256 + tid] = acc * inv;
}

// ------------- launch -------------
extern "C" void kernel_launch(void* const* d_in, const int* in_sizes, int n_in,
                              void* d_out, int out_size)
{
    const float* X      = (const float*)d_in[0];
    const float* wih0f  = (const float*)d_in[1];
    const float* whh0f  = (const float*)d_in[2];
    const float* bih0f  = (const float*)d_in[3];
    const float* bhh0f  = (const float*)d_in[4];
    const float* wih0b  = (const float*)d_in[5];
    const float* whh0b  = (const float*)d_in[6];
    const float* bih0b  = (const float*)d_in[7];
    const float* bhh0b  = (const float*)d_in[8];
    const float* wih1f  = (const float*)d_in[9];
    const float* whh1f  = (const float*)d_in[10];
    const float* bih1f  = (const float*)d_in[11];
    const float* bhh1f  = (const float*)d_in[12];
    const float* wih1b  = (const float*)d_in[13];
    const float* whh1b  = (const float*)d_in[14];
    const float* bih1b  = (const float*)d_in[15];
    const float* bhh1b  = (const float*)d_in[16];
    const float* attW   = (const float*)d_in[17];
    const float* attV   = (const float*)d_in[18];
    const float* headW  = (const float*)d_in[19];
    const float* headB  = (const float*)d_in[20];
    float* out = (float*)d_out;

    cudaFuncSetAttribute(scan_kernel, cudaFuncAttributeMaxDynamicSharedMemorySize, SCAN_SMEM);

    float *xT, *xwF, *xwB, *h0, *h1, *wT, *wi0, *wi1, *bsum, *att;
    __nv_bfloat16 *ahi, *alo, *whi, *wlo;
    cudaGetSymbolAddress((void**)&xT,  g_xT);
    cudaGetSymbolAddress((void**)&xwF, g_xwF);
    cudaGetSymbolAddress((void**)&xwB, g_xwB);
    cudaGetSymbolAddress((void**)&h0,  g_h0);
    cudaGetSymbolAddress((void**)&h1,  g_h1);
    cudaGetSymbolAddress((void**)&wT,  g_wT);
    cudaGetSymbolAddress((void**)&wi0, g_wih0);
    cudaGetSymbolAddress((void**)&wi1, g_wih1);
    cudaGetSymbolAddress((void**)&bsum,g_bsum);
    cudaGetSymbolAddress((void**)&att, g_att);
    cudaGetSymbolAddress((void**)&ahi, g_ahi);
    cudaGetSymbolAddress((void**)&alo, g_alo);
    cudaGetSymbolAddress((void**)&whi, g_whi);
    cudaGetSymbolAddress((void**)&wlo, g_wlo);

    // prep: reorder weights into gate-interleaved layouts, fold biases
    reorder_wih<<<(G4*Cc+255)/256, 256>>>(wih0f, wi0,            Cc);
    reorder_wih<<<(G4*Cc+255)/256, 256>>>(wih0b, wi0 + G4*Cc,    Cc);
    reorder_wih<<<(G4*256+255)/256,256>>>(wih1f, wi1,            256);
    reorder_wih<<<(G4*256+255)/256,256>>>(wih1b, wi1 + G4*256,   256);
    reorder_whh<<<(Hh*G4+255)/256, 256>>>(whh0f, wT + 0*Hh*G4);
    reorder_whh<<<(Hh*G4+255)/256, 256>>>(whh0b, wT + 1*Hh*G4);
    reorder_whh<<<(Hh*G4+255)/256, 256>>>(whh1f, wT + 2*Hh*G4);
    reorder_whh<<<(Hh*G4+255)/256, 256>>>(whh1b, wT + 3*Hh*G4);
    fold_b<<<2,256>>>(bih0f, bhh0f, bsum + 0*G4);
    fold_b<<<2,256>>>(bih0b, bhh0b, bsum + 1*G4);
    fold_b<<<2,256>>>(bih1f, bhh1f, bsum + 2*G4);
    fold_b<<<2,256>>>(bih1b, bhh1b, bsum + 3*G4);

    // weight bf16 splits
    conv_split<<<(512*KP0+255)/256,256>>>(wi0,          whi+WOFF0F, wlo+WOFF0F, 512*KP0, Cc, KP0);
    conv_split<<<(512*KP0+255)/256,256>>>(wi0 + G4*Cc,  whi+WOFF0B, wlo+WOFF0B, 512*KP0, Cc, KP0);
    conv_split<<<(512*256+255)/256,256>>>(wi1,          whi+WOFF1F, wlo+WOFF1F, 512*256, 256, 256);
    conv_split<<<(512*256+255)/256,256>>>(wi1 + G4*256, whi+WOFF1B, wlo+WOFF1B, 512*256, 256, 256);
    conv_splitT<<<(256*256+255)/256,256>>>(attW, whi+WOFFATT, wlo+WOFFATT, 256, 256, 256);

    transposeX<<<dim3((Tt+31)/32,(Cc+31)/32,Bsz), dim3(32,8)>>>(X, xT);

    // layer 0
    {
        size_t tot = (size_t)BT*KP0;
        conv_split<<<(unsigned)((tot+255)/256),256>>>(xT, ahi, alo, tot, Cc, KP0);
    }
    dim3 g0(4, BT/128);
    mma_gemm<<<g0,256>>>(ahi, alo, whi+WOFF0F, wlo+WOFF0F, bsum + 0*G4, xwF, BT, G4, KP0, 0);
    mma_gemm<<<g0,256>>>(ahi, alo, whi+WOFF0B, wlo+WOFF0B, bsum + 1*G4, xwB, BT, G4, KP0, 0);
    scan_kernel<<<128,256,SCAN_SMEM>>>(xwF, xwB, wT + 0*Hh*G4, wT + 1*Hh*G4, h0);

    // layer 1
    {
        size_t tot = (size_t)BT*256;
        conv_split<<<(unsigned)((tot+255)/256),256>>>(h0, ahi, alo, tot, 256, 256);
    }
    mma_gemm<<<g0,256>>>(ahi, alo, whi+WOFF1F, wlo+WOFF1F, bsum + 2*G4, xwF, BT, G4, 256, 0);
    mma_gemm<<<g0,256>>>(ahi, alo, whi+WOFF1B, wlo+WOFF1B, bsum + 3*G4, xwB, BT, G4, 256, 0);
    scan_kernel<<<128,256,SCAN_SMEM>>>(xwF, xwB, wT + 2*Hh*G4, wT + 3*Hh*G4, h1);

    // attention u = tanh(h1 @ att_W)
    {
        size_t tot = (size_t)BT*256;
        conv_split<<<(unsigned)((tot+255)/256),256>>>(h1, ahi, alo, tot, 256, 256);
    }
    mma_gemm<<<dim3(2, BT/128),256>>>(ahi, alo, whi+WOFFATT, wlo+WOFFATT, (const float*)0, xwF, BT, 256, 256, 1);
    att_kernel<<<Bsz,256>>>(xwF, h1, attV, att);
    // head (fp32)
    gemm128<<<dim3((NCLS+127)/128,(Bsz+127)/128),256>>>(att, headW, headB, out, Bsz, NCLS, 256, 1, 0);
}

// round 9
// speedup vs baseline: 1.5428x; 1.5428x over previous
#include <cuda_runtime.h>
#include <cuda_bf16.h>
#include <cstdint>

#define Bsz 512
#define Cc  271
#define Tt  281
#define Hh  128
#define NCLS 1854
#define BT  (Bsz*Tt)      /* 143872 */
#define G4  512
#define KP0 288           /* padded K for layer0 (multiple of 32) */

typedef unsigned long long u64;
typedef unsigned int u32;

union F4 { float4 v; float f[4]; u64 d[2]; };

__device__ __forceinline__ u64 ffma2(u64 a, u64 b, u64 c){
    u64 d; asm("fma.rn.f32x2 %0, %1, %2, %3;" : "=l"(d) : "l"(a), "l"(b), "l"(c)); return d;
}
__device__ __forceinline__ float2 unpack2(u64 d){
    float lo, hi; asm("mov.b64 {%0, %1}, %2;" : "=f"(lo), "=f"(hi) : "l"(d));
    return make_float2(lo, hi);
}
__device__ __forceinline__ float sigf(float x){ return __fdividef(1.f, 1.f + __expf(-x)); }
__device__ __forceinline__ float tanh_(float x){ return 1.f - __fdividef(2.f, __expf(2.f*x) + 1.f); }

// ------------- device scratch -------------
__device__ float g_xT [(size_t)BT*Cc];
__device__ float g_xwF[(size_t)BT*G4];
__device__ float g_xwB[(size_t)BT*G4];
__device__ float g_h0 [(size_t)BT*2*Hh];
__device__ float g_h1 [(size_t)BT*2*Hh];
__device__ float g_wT [4*Hh*G4];          // 4x [128][512] gate-interleaved W_hh^T
__device__ float g_wih0[2*G4*Cc];
__device__ float g_wih1[2*G4*2*Hh];
__device__ float g_bsum[4*G4];
__device__ float g_att[Bsz*2*Hh];
// bf16 split buffers
__device__ __nv_bfloat16 g_ahi[(size_t)BT*KP0];
__device__ __nv_bfloat16 g_alo[(size_t)BT*KP0];
#define WOFF0F 0
#define WOFF0B (512*KP0)
#define WOFF1F (2*512*KP0)
#define WOFF1B (2*512*KP0 + 512*256)
#define WOFFATT (2*512*KP0 + 2*512*256)
#define WTOT (WOFFATT + 256*256)
__device__ __nv_bfloat16 g_whi[WTOT];
__device__ __nv_bfloat16 g_wlo[WTOT];

__device__ __forceinline__ int oldrow(int n){ return (n&3)*128 + (n>>2); }

// ------------- prep kernels -------------
__global__ void reorder_wih(const float* __restrict__ src, float* __restrict__ dst, int K){
    int i = blockIdx.x*256 + threadIdx.x;
    if (i >= G4*K) return;
    int n = i / K, k = i % K;
    dst[i] = src[oldrow(n)*K + k];
}
__global__ void reorder_whh(const float* __restrict__ src, float* __restrict__ dst){
    int i = blockIdx.x*256 + threadIdx.x;
    if (i >= Hh*G4) return;
    int k = i >> 9, n = i & 511;
    dst[i] = src[oldrow(n)*Hh + k];
}
__global__ void fold_b(const float* __restrict__ bi, const float* __restrict__ bh, float* __restrict__ dst){
    int n = blockIdx.x*256 + threadIdx.x;
    if (n >= G4) return;
    int o = oldrow(n);
    dst[n] = bi[o] + bh[o];
}

// ------------- fp32 -> bf16 hi/lo split (with K padding) -------------
__global__ void conv_split(const float* __restrict__ src, __nv_bfloat16* __restrict__ hi,
                           __nv_bfloat16* __restrict__ lo, size_t total, int Ks, int Kp){
    size_t i = (size_t)blockIdx.x*256 + threadIdx.x;
    if (i >= total) return;
    size_t r = i / Kp; int k = (int)(i - r*Kp);
    float v = (k < Ks) ? src[r*Ks + k] : 0.f;
    __nv_bfloat16 h = __float2bfloat16(v);
    hi[i] = h;
    lo[i] = __float2bfloat16(v - __bfloat162float(h));
}
__global__ void conv_splitT(const float* __restrict__ src, __nv_bfloat16* __restrict__ hi,
                            __nv_bfloat16* __restrict__ lo, int N, int Ks, int Kp){
    int i = blockIdx.x*256 + threadIdx.x;
    if (i >= N*Kp) return;
    int n = i / Kp, k = i % Kp;
    float v = (k < Ks) ? src[(size_t)k*N + n] : 0.f;
    __nv_bfloat16 h = __float2bfloat16(v);
    hi[i] = h;
    lo[i] = __float2bfloat16(v - __bfloat162float(h));
}

// ------------- transpose X[B,C,T] -> xT[B,T,C] -------------
__global__ void transposeX(const float* __restrict__ X, float* __restrict__ xT){
    __shared__ float tile[32][33];
    int b = blockIdx.z;
    int t0 = blockIdx.x*32, c0 = blockIdx.y*32;
    int tx = threadIdx.x, ty = threadIdx.y;
    const float* Xb = X + (size_t)b*Cc*Tt;
    float* xTb = xT + (size_t)b*Tt*Cc;
    #pragma unroll
    for (int i=0;i<32;i+=8){
        int c = c0+ty+i, t = t0+tx;
        if (c<Cc && t<Tt) tile[ty+i][tx] = Xb[(size_t)c*Tt + t];
    }
    __syncthreads();
    #pragma unroll
    for (int i=0;i<32;i+=8){
        int t = t0+ty+i, c = c0+tx;
        if (t<Tt && c<Cc) xTb[(size_t)t*Cc + c] = tile[tx][ty+i];
    }
}

// ------------- tensor-core GEMM, split-bf16 (3 passes), 32-wide K chunks -------
// C[M,N] = act(A[M,K] @ W[N,K]^T + bias).  M,N multiples of 128. Kp multiple of 32.
#define SST2 40                  /* smem row stride in halves (32 data + 8 pad) */
#define TSZ  (128*SST2)          /* halves per tile */
#define MMA_SMEM (2*4*TSZ*2)     /* bytes: 2 stages x 4 tiles */
__device__ __forceinline__ u32 smaddr(const void* p){ return (u32)__cvta_generic_to_shared(p); }
__device__ __forceinline__ void cpasync16(u32 s, const void* g){
    asm volatile("cp.async.cg.shared.global [%0], [%1], 16;" :: "r"(s), "l"(g));
}
__device__ __forceinline__ void ldsm4(u32* r, u32 a){
    asm volatile("ldmatrix.sync.aligned.m8n8.x4.shared.b16 {%0,%1,%2,%3}, [%4];"
        : "=r"(r[0]),"=r"(r[1]),"=r"(r[2]),"=r"(r[3]) : "r"(a));
}
__device__ __forceinline__ void mma16816(float* d, const u32* a, u32 b0, u32 b1){
    asm volatile("mma.sync.aligned.m16n8k16.row.col.f32.bf16.bf16.f32 "
        "{%0,%1,%2,%3}, {%4,%5,%6,%7}, {%8,%9}, {%0,%1,%2,%3};"
        : "+f"(d[0]),"+f"(d[1]),"+f"(d[2]),"+f"(d[3])
        : "r"(a[0]),"r"(a[1]),"r"(a[2]),"r"(a[3]), "r"(b0),"r"(b1));
}

__global__ __launch_bounds__(256,1)
void mma_gemm(const __nv_bfloat16* __restrict__ Ahi, const __nv_bfloat16* __restrict__ Alo,
              const __nv_bfloat16* __restrict__ Whi, const __nv_bfloat16* __restrict__ Wlo,
              const float* __restrict__ bias, float* __restrict__ C,
              int M, int N, int Kp, int act)
{
    extern __shared__ __align__(16) __nv_bfloat16 sm[];   // [2][4][TSZ]
    int tid = threadIdx.x;
    int wid = tid>>5, lane = tid&31;
    int m0 = blockIdx.y*128, n0 = blockIdx.x*128;
    int wm = (wid>>2)*64, wn = (wid&3)*32;

    float acc[4][4][4];
    #pragma unroll
    for (int i=0;i<4;i++)
      #pragma unroll
      for (int j=0;j<4;j++)
        #pragma unroll
        for (int q=0;q<4;q++) acc[i][j][q] = 0.f;

    const __nv_bfloat16* gsrc[4];
    gsrc[0] = Ahi + (size_t)m0*Kp;
    gsrc[1] = Alo + (size_t)m0*Kp;
    gsrc[2] = Whi + (size_t)n0*Kp;
    gsrc[3] = Wlo + (size_t)n0*Kp;

    int lrow = tid>>2, lseg = tid&3;       // 128 rows x 4 x 16B segs per tile
    int NC = Kp >> 5;                       // 32-wide chunks

    {   // prologue: chunk 0 -> stage 0
        #pragma unroll
        for (int t=0;t<4;t++){
            #pragma unroll
            for (int i=0;i<2;i++){
                int u = tid + i*256;
                int row = u>>2, seg = u&3;
                cpasync16(smaddr(&sm[t*TSZ + row*SST2 + seg*8]),
                          gsrc[t] + (size_t)row*Kp + seg*8);
            }
        }
        asm volatile("cp.async.commit_group;" ::: "memory");
    }

    int ar = lane & 15;
    int ac = (lane >> 4) * 8;
    int brn = (lane & 7) + ((lane & 16) ? 8 : 0);
    int bc  = (lane & 8) ? 8 : 0;

    for (int c=0;c<NC;c++){
        if (c+1 < NC){
            int k0 = (c+1)*32, s = (c+1)&1;
            #pragma unroll
            for (int t=0;t<4;t++){
                #pragma unroll
                for (int i=0;i<2;i++){
                    int u = tid + i*256;
                    int row = u>>2, seg = u&3;
                    cpasync16(smaddr(&sm[s*4*TSZ + t*TSZ + row*SST2 + seg*8]),
                              gsrc[t] + (size_t)row*Kp + k0 + seg*8);
                }
            }
            asm volatile("cp.async.commit_group;" ::: "memory");
            asm volatile("cp.async.wait_group 1;" ::: "memory");
        } else {
            asm volatile("cp.async.wait_group 0;" ::: "memory");
        }
        __syncthreads();
        int s = c & 1;
        const __nv_bfloat16* tA_hi = sm + s*4*TSZ + 0*TSZ;
        const __nv_bfloat16* tA_lo = sm + s*4*TSZ + 1*TSZ;
        const __nv_bfloat16* tW_hi = sm + s*4*TSZ + 2*TSZ;
        const __nv_bfloat16* tW_lo = sm + s*4*TSZ + 3*TSZ;

        #pragma unroll
        for (int ks=0; ks<2; ks++){
            int ko = ks*16;
            u32 Af[4][4], Whf[2][4], Wlf[2][4];
            #pragma unroll
            for (int mi=0;mi<4;mi++)
                ldsm4(Af[mi], smaddr(&tA_hi[(wm + mi*16 + ar)*SST2 + ko + ac]));
            #pragma unroll
            for (int g=0;g<2;g++)
                ldsm4(Whf[g], smaddr(&tW_hi[(wn + g*16 + brn)*SST2 + ko + bc]));
            // pass 1: Ahi * Whi
            #pragma unroll
            for (int mi=0;mi<4;mi++)
                #pragma unroll
                for (int ni=0;ni<4;ni++)
                    mma16816(acc[mi][ni], Af[mi], Whf[ni>>1][(ni&1)*2], Whf[ni>>1][(ni&1)*2+1]);
            // pass 2: Ahi * Wlo
            #pragma unroll
            for (int g=0;g<2;g++)
                ldsm4(Wlf[g], smaddr(&tW_lo[(wn + g*16 + brn)*SST2 + ko + bc]));
            #pragma unroll
            for (int mi=0;mi<4;mi++)
                #pragma unroll
                for (int ni=0;ni<4;ni++)
                    mma16816(acc[mi][ni], Af[mi], Wlf[ni>>1][(ni&1)*2], Wlf[ni>>1][(ni&1)*2+1]);
            // pass 3: Alo * Whi
            #pragma unroll
            for (int mi=0;mi<4;mi++)
                ldsm4(Af[mi], smaddr(&tA_lo[(wm + mi*16 + ar)*SST2 + ko + ac]));
            #pragma unroll
            for (int mi=0;mi<4;mi++)
                #pragma unroll
                for (int ni=0;ni<4;ni++)
                    mma16816(acc[mi][ni], Af[mi], Whf[ni>>1][(ni&1)*2], Whf[ni>>1][(ni&1)*2+1]);
        }
        __syncthreads();
    }

    // epilogue
    int er = lane>>2, ec = (lane&3)*2;
    #pragma unroll
    for (int mi=0;mi<4;mi++){
        #pragma unroll
        for (int ni=0;ni<4;ni++){
            int gm = m0 + wm + mi*16 + er;
            int gn = n0 + wn + ni*8 + ec;
            float b0 = bias ? bias[gn]   : 0.f;
            float b1 = bias ? bias[gn+1] : 0.f;
            float v0 = acc[mi][ni][0] + b0;
            float v1 = acc[mi][ni][1] + b1;
            float v2 = acc[mi][ni][2] + b0;
            float v3 = acc[mi][ni][3] + b1;
            if (act){ v0 = tanh_(v0); v1 = tanh_(v1); v2 = tanh_(v2); v3 = tanh_(v3); }
            *(float2*)&C[(size_t)gm*N + gn]     = make_float2(v0, v1);
            *(float2*)&C[(size_t)(gm+8)*N + gn] = make_float2(v2, v3);
        }
    }
}

// ------------- fp32 GEMM (head only) -------------
__global__ __launch_bounds__(256,2)
void gemm128(const float* __restrict__ A, const float* __restrict__ B,
             const float* __restrict__ bias, float* __restrict__ C,
             int M, int N, int K, int transB, int act)
{
    __shared__ float As2[16][264];
    __shared__ float Bs[16][132];
    int row0 = blockIdx.y*128, col0 = blockIdx.x*128;
    int tid = threadIdx.x;
    int tm = tid >> 4, tn = tid & 15;
    u64 acc[8][4];
    #pragma unroll
    for (int i=0;i<8;i++)
        #pragma unroll
        for (int j=0;j<4;j++) acc[i][j] = 0ull;

    for (int k0=0;k0<K;k0+=16){
        #pragma unroll
        for (int i=0;i<8;i++){
            int idx = tid + i*256;
            int r = idx >> 4, kk = idx & 15;
            int gr = row0+r, gk = k0+kk;
            float v = (gr<M && gk<K) ? A[(size_t)gr*K + gk] : 0.f;
            *(float2*)&As2[kk][2*r] = make_float2(v, v);
        }
        if (transB){
            #pragma unroll
            for (int i=0;i<8;i++){
                int idx = tid + i*256;
                int nn = idx >> 4, kk = idx & 15;
                int gk = k0+kk, gn = col0+nn;
                Bs[kk][nn] = (gk<K && gn<N) ? B[(size_t)gn*K+gk] : 0.f;
            }
        } else {
            #pragma unroll
            for (int i=0;i<8;i++){
                int idx = tid + i*256;
                int nn = idx & 127, kk = idx >> 7;
                int gk = k0+kk, gn = col0+nn;
                Bs[kk][nn] = (gk<K && gn<N) ? B[(size_t)gk*N+gn] : 0.f;
            }
        }
        __syncthreads();
        #pragma unroll
        for (int kk=0;kk<16;kk++){
            F4 b0, b1, a0, a1, a2, a3;
            b0.v = *(const float4*)&Bs[kk][tn*8];
            b1.v = *(const float4*)&Bs[kk][tn*8+4];
            a0.v = *(const float4*)&As2[kk][tm*16];
            a1.v = *(const float4*)&As2[kk][tm*16+4];
            a2.v = *(const float4*)&As2[kk][tm*16+8];
            a3.v = *(const float4*)&As2[kk][tm*16+12];
            u64 bd[4] = { b0.d[0], b0.d[1], b1.d[0], b1.d[1] };
            u64 ad[8] = { a0.d[0], a0.d[1], a1.d[0], a1.d[1],
                          a2.d[0], a2.d[1], a3.d[0], a3.d[1] };
            #pragma unroll
            for (int i=0;i<8;i++)
                #pragma unroll
                for (int j=0;j<4;j++)
                    acc[i][j] = ffma2(ad[i], bd[j], acc[i][j]);
        }
        __syncthreads();
    }
    #pragma unroll
    for (int i=0;i<8;i++){
        int gr = row0 + tm*8 + i;
        if (gr >= M) continue;
        #pragma unroll
        for (int j=0;j<4;j++){
            float2 v = unpack2(acc[i][j]);
            int gn = col0 + tn*8 + j*2;
            if (gn < N){
                float x = v.x + (bias ? bias[gn] : 0.f);
                if (act) x = tanh_(x);
                C[(size_t)gr*N + gn] = x;
            }
            if (gn+1 < N){
                float y = v.y + (bias ? bias[gn+1] : 0.f);
                if (act) y = tanh_(y);
                C[(size_t)gr*N + gn+1] = y;
            }
        }
    }
}

// ------------- LSTM scan (prefetch + double-buffered h) -------------
#define HS 20
#define SCAN_SMEM ((64*G4 + 2*128*HS)*4)

__global__ __launch_bounds__(256,1)
void scan_kernel(const float* __restrict__ xwFp, const float* __restrict__ xwBp,
                 const float* __restrict__ wTF, const float* __restrict__ wTB,
                 float* __restrict__ hout)
{
    extern __shared__ float smf[];
    float* Ws  = smf;
    float* hsA = smf + 64*G4;
    float* hsB = hsA + 128*HS;
    int tid = threadIdx.x;
    int dir = blockIdx.x >> 6;
    int grp = blockIdx.x & 63;
    int b0 = grp*8;
    const float* xw = dir ? xwBp : xwFp;
    const float* wD = dir ? wTB : wTF;
    int hOff = dir*128;
    int h  = tid & 127;
    int rg = tid >> 7;

    for (int i=tid;i<64*G4;i+=256) Ws[i] = wD[i];
    for (int i=tid;i<2*128*HS;i+=256) hsA[i] = 0.f;
    float cst[4] = {0.f,0.f,0.f,0.f};

    const float* xp[4];
    float* hop[4];
    #pragma unroll
    for (int r=0;r<4;r++){
        xp[r]  = xw   + ((size_t)(b0+4*rg+r)*Tt)*G4 + 4*h;
        hop[r] = hout + ((size_t)(b0+4*rg+r)*Tt)*256 + hOff + h;
    }
    __syncthreads();

    int t0 = dir ? (Tt-1) : 0;
    F4 xvc[4];
    #pragma unroll
    for (int r=0;r<4;r++) xvc[r].v = *(const float4*)&xp[r][(size_t)t0*G4];

    for (int s=0;s<Tt;s++){
        int t = dir ? (Tt-1-s) : s;
        float* hsR = (s&1) ? hsB : hsA;
        float* hsW = (s&1) ? hsA : hsB;

        F4 xvn[4];
        if (s+1 < Tt){
            int tn_ = dir ? (Tt-2-s) : (s+1);
            #pragma unroll
            for (int r=0;r<4;r++) xvn[r].v = *(const float4*)&xp[r][(size_t)tn_*G4];
        }

        u64 aIF[4] = {0,0,0,0}, aGO[4] = {0,0,0,0};
        #pragma unroll 8
        for (int k=0;k<64;k++){
            F4 w;  w.v  = *(const float4*)&Ws[k*G4 + 4*h];
            F4 p0; p0.v = *(const float4*)&hsR[k*HS + 8*rg];
            F4 p1; p1.v = *(const float4*)&hsR[k*HS + 8*rg + 4];
            aIF[0]=ffma2(p0.d[0], w.d[0], aIF[0]); aGO[0]=ffma2(p0.d[0], w.d[1], aGO[0]);
            aIF[1]=ffma2(p0.d[1], w.d[0], aIF[1]); aGO[1]=ffma2(p0.d[1], w.d[1], aGO[1]);
            aIF[2]=ffma2(p1.d[0], w.d[0], aIF[2]); aGO[2]=ffma2(p1.d[0], w.d[1], aGO[2]);
            aIF[3]=ffma2(p1.d[1], w.d[0], aIF[3]); aGO[3]=ffma2(p1.d[1], w.d[1], aGO[3]);
        }
        for (int kb=64;kb<128;kb+=8){
            F4 w[8];
            #pragma unroll
            for (int j=0;j<8;j++) w[j].v = *(const float4*)&wD[(size_t)(kb+j)*G4 + 4*h];
            #pragma unroll
            for (int j=0;j<8;j++){
                int k = kb+j;
                F4 p0; p0.v = *(const float4*)&hsR[k*HS + 8*rg];
                F4 p1; p1.v = *(const float4*)&hsR[k*HS + 8*rg + 4];
                aIF[0]=ffma2(p0.d[0], w[j].d[0], aIF[0]); aGO[0]=ffma2(p0.d[0], w[j].d[1], aGO[0]);
                aIF[1]=ffma2(p0.d[1], w[j].d[0], aIF[1]); aGO[1]=ffma2(p0.d[1], w[j].d[1], aGO[1]);
                aIF[2]=ffma2(p1.d[0], w[j].d[0], aIF[2]); aGO[2]=ffma2(p1.d[0], w[j].d[1], aGO[2]);
                aIF[3]=ffma2(p1.d[1], w[j].d[0], aIF[3]); aGO[3]=ffma2(p1.d[1], w[j].d[1], aGO[3]);
            }
        }
        float hnew[4];
        #pragma unroll
        for (int r=0;r<4;r++){
            float2 v1 = unpack2(aIF[r]);
            float2 v2 = unpack2(aGO[r]);
            float gi = v1.x + xvc[r].f[0];
            float gf = v1.y + xvc[r].f[1];
            float gg = v2.x + xvc[r].f[2];
            float go = v2.y + xvc[r].f[3];
            float cc = sigf(gf)*cst[r] + sigf(gi)*tanh_(gg);
            cst[r] = cc;
            hnew[r] = sigf(go)*tanh_(cc);
        }
        #pragma unroll
        for (int r=0;r<4;r++){
            *(float2*)&hsW[h*HS + 2*(4*rg+r)] = make_float2(hnew[r], hnew[r]);
            hop[r][(size_t)t*256] = hnew[r];
        }
        __syncthreads();
        #pragma unroll
        for (int r=0;r<4;r++) xvc[r] = xvn[r];
    }
}

// ------------- attention -------------
__global__ __launch_bounds__(256,1)
void att_kernel(const float* __restrict__ u, const float* __restrict__ h1,
                const float* __restrict__ v, float* __restrict__ att)
{
    __shared__ float sa[Tt];
    __shared__ float red[256];
    int b = blockIdx.x, tid = threadIdx.x;
    for (int t = tid; t < Tt; t += 256){
        const float* ur = u + ((size_t)b*Tt + t)*256;
        float s = 0.f;
        #pragma unroll 8
        for (int k=0;k<256;k++) s += ur[k]*v[k];
        sa[t] = s;
    }
    __syncthreads();
    float m = -3.4e38f;
    for (int t=tid;t<Tt;t+=256) m = fmaxf(m, sa[t]);
    red[tid] = m; __syncthreads();
    for (int off=128; off>0; off>>=1){ if (tid<off) red[tid]=fmaxf(red[tid],red[tid+off]); __syncthreads(); }
    float mx = red[0]; __syncthreads();
    float sum = 0.f;
    for (int t=tid;t<Tt;t+=256){ float e = __expf(sa[t]-mx); sa[t]=e; sum+=e; }
    red[tid] = sum; __syncthreads();
    for (int off=128; off>0; off>>=1){ if (tid<off) red[tid]+=red[tid+off]; __syncthreads(); }
    float inv = __fdividef(1.f, red[0]);
    __syncthreads();
    float acc = 0.f;
    const float* hb = h1 + (size_t)b*Tt*256 + tid;
    #pragma unroll 4
    for (int t=0;t<Tt;t++) acc += hb[(size_t)t*256] * sa[t];
    att[b*256 + tid] = acc * inv;
}

// ------------- launch -------------
extern "C" void kernel_launch(void* const* d_in, const int* in_sizes, int n_in,
                              void* d_out, int out_size)
{
    const float* X      = (const float*)d_in[0];
    const float* wih0f  = (const float*)d_in[1];
    const float* whh0f  = (const float*)d_in[2];
    const float* bih0f  = (const float*)d_in[3];
    const float* bhh0f  = (const float*)d_in[4];
    const float* wih0b  = (const float*)d_in[5];
    const float* whh0b  = (const float*)d_in[6];
    const float* bih0b  = (const float*)d_in[7];
    const float* bhh0b  = (const float*)d_in[8];
    const float* wih1f  = (const float*)d_in[9];
    const float* whh1f  = (const float*)d_in[10];
    const float* bih1f  = (const float*)d_in[11];
    const float* bhh1f  = (const float*)d_in[12];
    const float* wih1b  = (const float*)d_in[13];
    const float* whh1b  = (const float*)d_in[14];
    const float* bih1b  = (const float*)d_in[15];
    const float* bhh1b  = (const float*)d_in[16];
    const float* attW   = (const float*)d_in[17];
    const float* attV   = (const float*)d_in[18];
    const float* headW  = (const float*)d_in[19];
    const float* headB  = (const float*)d_in[20];
    float* out = (float*)d_out;

    cudaFuncSetAttribute(scan_kernel, cudaFuncAttributeMaxDynamicSharedMemorySize, SCAN_SMEM);
    cudaFuncSetAttribute(mma_gemm,    cudaFuncAttributeMaxDynamicSharedMemorySize, MMA_SMEM);

    float *xT, *xwF, *xwB, *h0, *h1, *wT, *wi0, *wi1, *bsum, *att;
    __nv_bfloat16 *ahi, *alo, *whi, *wlo;
    cudaGetSymbolAddress((void**)&xT,  g_xT);
    cudaGetSymbolAddress((void**)&xwF, g_xwF);
    cudaGetSymbolAddress((void**)&xwB, g_xwB);
    cudaGetSymbolAddress((void**)&h0,  g_h0);
    cudaGetSymbolAddress((void**)&h1,  g_h1);
    cudaGetSymbolAddress((void**)&wT,  g_wT);
    cudaGetSymbolAddress((void**)&wi0, g_wih0);
    cudaGetSymbolAddress((void**)&wi1, g_wih1);
    cudaGetSymbolAddress((void**)&bsum,g_bsum);
    cudaGetSymbolAddress((void**)&att, g_att);
    cudaGetSymbolAddress((void**)&ahi, g_ahi);
    cudaGetSymbolAddress((void**)&alo, g_alo);
    cudaGetSymbolAddress((void**)&whi, g_whi);
    cudaGetSymbolAddress((void**)&wlo, g_wlo);

    // prep: reorder weights into gate-interleaved layouts, fold biases
    reorder_wih<<<(G4*Cc+255)/256, 256>>>(wih0f, wi0,            Cc);
    reorder_wih<<<(G4*Cc+255)/256, 256>>>(wih0b, wi0 + G4*Cc,    Cc);
    reorder_wih<<<(G4*256+255)/256,256>>>(wih1f, wi1,            256);
    reorder_wih<<<(G4*256+255)/256,256>>>(wih1b, wi1 + G4*256,   256);
    reorder_whh<<<(Hh*G4+255)/256, 256>>>(whh0f, wT + 0*Hh*G4);
    reorder_whh<<<(Hh*G4+255)/256, 256>>>(whh0b, wT + 1*Hh*G4);
    reorder_whh<<<(Hh*G4+255)/256, 256>>>(whh1f, wT + 2*Hh*G4);
    reorder_whh<<<(Hh*G4+255)/256, 256>>>(whh1b, wT + 3*Hh*G4);
    fold_b<<<2,256>>>(bih0f, bhh0f, bsum + 0*G4);
    fold_b<<<2,256>>>(bih0b, bhh0b, bsum + 1*G4);
    fold_b<<<2,256>>>(bih1f, bhh1f, bsum + 2*G4);
    fold_b<<<2,256>>>(bih1b, bhh1b, bsum + 3*G4);

    // weight bf16 splits
    conv_split<<<(512*KP0+255)/256,256>>>(wi0,          whi+WOFF0F, wlo+WOFF0F, 512*KP0, Cc, KP0);
    conv_split<<<(512*KP0+255)/256,256>>>(wi0 + G4*Cc,  whi+WOFF0B, wlo+WOFF0B, 512*KP0, Cc, KP0);
    conv_split<<<(512*256+255)/256,256>>>(wi1,          whi+WOFF1F, wlo+WOFF1F, 512*256, 256, 256);
    conv_split<<<(512*256+255)/256,256>>>(wi1 + G4*256, whi+WOFF1B, wlo+WOFF1B, 512*256, 256, 256);
    conv_splitT<<<(256*256+255)/256,256>>>(attW, whi+WOFFATT, wlo+WOFFATT, 256, 256, 256);

    transposeX<<<dim3((Tt+31)/32,(Cc+31)/32,Bsz), dim3(32,8)>>>(X, xT);

    // layer 0
    {
        size_t tot = (size_t)BT*KP0;
        conv_split<<<(unsigned)((tot+255)/256),256>>>(xT, ahi, alo, tot, Cc, KP0);
    }
    dim3 g0(4, BT/128);
    mma_gemm<<<g0,256,MMA_SMEM>>>(ahi, alo, whi+WOFF0F, wlo+WOFF0F, bsum + 0*G4, xwF, BT, G4, KP0, 0);
    mma_gemm<<<g0,256,MMA_SMEM>>>(ahi, alo, whi+WOFF0B, wlo+WOFF0B, bsum + 1*G4, xwB, BT, G4, KP0, 0);
    scan_kernel<<<128,256,SCAN_SMEM>>>(xwF, xwB, wT + 0*Hh*G4, wT + 1*Hh*G4, h0);

    // layer 1
    {
        size_t tot = (size_t)BT*256;
        conv_split<<<(unsigned)((tot+255)/256),256>>>(h0, ahi, alo, tot, 256, 256);
    }
    mma_gemm<<<g0,256,MMA_SMEM>>>(ahi, alo, whi+WOFF1F, wlo+WOFF1F, bsum + 2*G4, xwF, BT, G4, 256, 0);
    mma_gemm<<<g0,256,MMA_SMEM>>>(ahi, alo, whi+WOFF1B, wlo+WOFF1B, bsum + 3*G4, xwB, BT, G4, 256, 0);
    scan_kernel<<<128,256,SCAN_SMEM>>>(xwF, xwB, wT + 2*Hh*G4, wT + 3*Hh*G4, h1);

    // attention u = tanh(h1 @ att_W)
    {
        size_t tot = (size_t)BT*256;
        conv_split<<<(unsigned)((tot+255)/256),256>>>(h1, ahi, alo, tot, 256, 256);
    }
    mma_gemm<<<dim3(2, BT/128),256,MMA_SMEM>>>(ahi, alo, whi+WOFFATT, wlo+WOFFATT, (const float*)0, xwF, BT, 256, 256, 1);
    att_kernel<<<Bsz,256>>>(xwF, h1, attV, att);
    // head (fp32)
    gemm128<<<dim3((NCLS+127)/128,(Bsz+127)/128),256>>>(att, headW, headB, out, Bsz, NCLS, 256, 1, 0);
}

// round 10
// speedup vs baseline: 1.6619x; 1.0772x over previous
#include <cuda_runtime.h>
#include <cuda_bf16.h>
#include <cstdint>

#define Bsz 512
#define Cc  271
#define Tt  281
#define Hh  128
#define NCLS 1854
#define BT  (Bsz*Tt)      /* 143872 */
#define G4  512
#define KP0 320           /* padded K for layer0 (multiple of 64) */

typedef unsigned long long u64;
typedef unsigned int u32;

union F4 { float4 v; float f[4]; u64 d[2]; };

__device__ __forceinline__ u64 ffma2(u64 a, u64 b, u64 c){
    u64 d; asm("fma.rn.f32x2 %0, %1, %2, %3;" : "=l"(d) : "l"(a), "l"(b), "l"(c)); return d;
}
__device__ __forceinline__ float2 unpack2(u64 d){
    float lo, hi; asm("mov.b64 {%0, %1}, %2;" : "=f"(lo), "=f"(hi) : "l"(d));
    return make_float2(lo, hi);
}
__device__ __forceinline__ float sigf(float x){ return __fdividef(1.f, 1.f + __expf(-x)); }
__device__ __forceinline__ float tanh_(float x){ return 1.f - __fdividef(2.f, __expf(2.f*x) + 1.f); }

// ------------- device scratch -------------
__device__ float g_xwF[(size_t)BT*G4];
__device__ float g_xwB[(size_t)BT*G4];
__device__ float g_h1 [(size_t)BT*2*Hh];
__device__ float g_wT [4*Hh*G4];          // 4x [128][512] gate-interleaved W_hh^T
__device__ float g_wih0[2*G4*Cc];
__device__ float g_wih1[2*G4*2*Hh];
__device__ float g_bsum[4*G4];
__device__ float g_att[Bsz*2*Hh];
// bf16 split buffers (A operand: x for layer0, h for layer1/att)
__device__ __nv_bfloat16 g_ahi[(size_t)BT*KP0];
__device__ __nv_bfloat16 g_alo[(size_t)BT*KP0];
#define WOFF0F 0
#define WOFF0B (512*KP0)
#define WOFF1F (2*512*KP0)
#define WOFF1B (2*512*KP0 + 512*256)
#define WOFFATT (2*512*KP0 + 2*512*256)
#define WTOT (WOFFATT + 256*256)
__device__ __nv_bfloat16 g_whi[WTOT];
__device__ __nv_bfloat16 g_wlo[WTOT];

__device__ __forceinline__ int oldrow(int n){ return (n&3)*128 + (n>>2); }

// ------------- prep kernels -------------
__global__ void reorder_wih(const float* __restrict__ src, float* __restrict__ dst, int K){
    int i = blockIdx.x*256 + threadIdx.x;
    if (i >= G4*K) return;
    int n = i / K, k = i % K;
    dst[i] = src[oldrow(n)*K + k];
}
__global__ void reorder_whh(const float* __restrict__ src, float* __restrict__ dst){
    int i = blockIdx.x*256 + threadIdx.x;
    if (i >= Hh*G4) return;
    int k = i >> 9, n = i & 511;
    dst[i] = src[oldrow(n)*Hh + k];
}
__global__ void fold_b(const float* __restrict__ bi, const float* __restrict__ bh, float* __restrict__ dst){
    int n = blockIdx.x*256 + threadIdx.x;
    if (n >= G4) return;
    int o = oldrow(n);
    dst[n] = bi[o] + bh[o];
}

// ------------- fp32 -> bf16 hi/lo split (weights only) -------------
__global__ void conv_split(const float* __restrict__ src, __nv_bfloat16* __restrict__ hi,
                           __nv_bfloat16* __restrict__ lo, size_t total, int Ks, int Kp){
    size_t i = (size_t)blockIdx.x*256 + threadIdx.x;
    if (i >= total) return;
    size_t r = i / Kp; int k = (int)(i - r*Kp);
    float v = (k < Ks) ? src[r*Ks + k] : 0.f;
    __nv_bfloat16 h = __float2bfloat16(v);
    hi[i] = h;
    lo[i] = __float2bfloat16(v - __bfloat162float(h));
}
__global__ void conv_splitT(const float* __restrict__ src, __nv_bfloat16* __restrict__ hi,
                            __nv_bfloat16* __restrict__ lo, int N, int Ks, int Kp){
    int i = blockIdx.x*256 + threadIdx.x;
    if (i >= N*Kp) return;
    int n = i / Kp, k = i % Kp;
    float v = (k < Ks) ? src[(size_t)k*N + n] : 0.f;
    __nv_bfloat16 h = __float2bfloat16(v);
    hi[i] = h;
    lo[i] = __float2bfloat16(v - __bfloat162float(h));
}

// ------------- transpose X[B,C,T] -> split bf16 A[B*T, KP0] -------------
__global__ void transpose_split(const float* __restrict__ X,
                                __nv_bfloat16* __restrict__ hi,
                                __nv_bfloat16* __restrict__ lo){
    __shared__ float tile[32][33];
    int b = blockIdx.z;
    int t0 = blockIdx.x*32, c0 = blockIdx.y*32;
    int tx = threadIdx.x, ty = threadIdx.y;
    const float* Xb = X + (size_t)b*Cc*Tt;
    #pragma unroll
    for (int i=0;i<32;i+=8){
        int c = c0+ty+i, t = t0+tx;
        tile[ty+i][tx] = (c<Cc && t<Tt) ? Xb[(size_t)c*Tt + t] : 0.f;
    }
    __syncthreads();
    #pragma unroll
    for (int i=0;i<32;i+=8){
        int t = t0+ty+i, c = c0+tx;
        if (t<Tt){
            float v = tile[tx][ty+i];
            __nv_bfloat16 h = __float2bfloat16(v);
            size_t idx = ((size_t)b*Tt + t)*KP0 + c;
            hi[idx] = h;
            lo[idx] = __float2bfloat16(v - __bfloat162float(h));
        }
    }
}

// ------------- tensor-core GEMM, split-bf16 (3 passes), 64-wide K chunks -------
// C[M,N] = act(A[M,K] @ W[N,K]^T + bias).  M,N multiples of 128. Kp multiple of 64.
#define SST2 72                  /* smem row stride in halves (64 data + 8 pad) */
#define TSZ  (128*SST2)          /* halves per tile */
#define MMA_SMEM (2*4*TSZ*2)     /* bytes: 2 stages x 4 tiles = 147456 */
__device__ __forceinline__ u32 smaddr(const void* p){ return (u32)__cvta_generic_to_shared(p); }
__device__ __forceinline__ void cpasync16(u32 s, const void* g){
    asm volatile("cp.async.cg.shared.global [%0], [%1], 16;" :: "r"(s), "l"(g));
}
__device__ __forceinline__ void ldsm4(u32* r, u32 a){
    asm volatile("ldmatrix.sync.aligned.m8n8.x4.shared.b16 {%0,%1,%2,%3}, [%4];"
        : "=r"(r[0]),"=r"(r[1]),"=r"(r[2]),"=r"(r[3]) : "r"(a));
}
__device__ __forceinline__ void mma16816(float* d, const u32* a, u32 b0, u32 b1){
    asm volatile("mma.sync.aligned.m16n8k16.row.col.f32.bf16.bf16.f32 "
        "{%0,%1,%2,%3}, {%4,%5,%6,%7}, {%8,%9}, {%0,%1,%2,%3};"
        : "+f"(d[0]),"+f"(d[1]),"+f"(d[2]),"+f"(d[3])
        : "r"(a[0]),"r"(a[1]),"r"(a[2]),"r"(a[3]), "r"(b0),"r"(b1));
}

__global__ __launch_bounds__(256,1)
void mma_gemm(const __nv_bfloat16* __restrict__ Ahi, const __nv_bfloat16* __restrict__ Alo,
              const __nv_bfloat16* __restrict__ Whi, const __nv_bfloat16* __restrict__ Wlo,
              const float* __restrict__ bias, float* __restrict__ C,
              int M, int N, int Kp, int act)
{
    extern __shared__ __align__(16) __nv_bfloat16 sm[];   // [2][4][TSZ]
    int tid = threadIdx.x;
    int wid = tid>>5, lane = tid&31;
    int m0 = blockIdx.y*128, n0 = blockIdx.x*128;
    int wm = (wid>>2)*64, wn = (wid&3)*32;

    float acc[4][4][4];
    #pragma unroll
    for (int i=0;i<4;i++)
      #pragma unroll
      for (int j=0;j<4;j++)
        #pragma unroll
        for (int q=0;q<4;q++) acc[i][j][q] = 0.f;

    const __nv_bfloat16* gsrc[4];
    gsrc[0] = Ahi + (size_t)m0*Kp;
    gsrc[1] = Alo + (size_t)m0*Kp;
    gsrc[2] = Whi + (size_t)n0*Kp;
    gsrc[3] = Wlo + (size_t)n0*Kp;

    int NC = Kp >> 6;                       // 64-wide chunks

    {   // prologue: chunk 0 -> stage 0
        #pragma unroll
        for (int t=0;t<4;t++){
            #pragma unroll
            for (int i=0;i<4;i++){
                int u = tid + i*256;
                int row = u>>3, seg = u&7;
                cpasync16(smaddr(&sm[t*TSZ + row*SST2 + seg*8]),
                          gsrc[t] + (size_t)row*Kp + seg*8);
            }
        }
        asm volatile("cp.async.commit_group;" ::: "memory");
    }

    int ar = lane & 15;
    int ac = (lane >> 4) * 8;
    int brn = (lane & 7) + ((lane & 16) ? 8 : 0);
    int bc  = (lane & 8) ? 8 : 0;

    for (int c=0;c<NC;c++){
        if (c+1 < NC){
            int k0 = (c+1)*64, s = (c+1)&1;
            #pragma unroll
            for (int t=0;t<4;t++){
                #pragma unroll
                for (int i=0;i<4;i++){
                    int u = tid + i*256;
                    int row = u>>3, seg = u&7;
                    cpasync16(smaddr(&sm[s*4*TSZ + t*TSZ + row*SST2 + seg*8]),
                              gsrc[t] + (size_t)row*Kp + k0 + seg*8);
                }
            }
            asm volatile("cp.async.commit_group;" ::: "memory");
            asm volatile("cp.async.wait_group 1;" ::: "memory");
        } else {
            asm volatile("cp.async.wait_group 0;" ::: "memory");
        }
        __syncthreads();
        int s = c & 1;
        const __nv_bfloat16* tA_hi = sm + s*4*TSZ + 0*TSZ;
        const __nv_bfloat16* tA_lo = sm + s*4*TSZ + 1*TSZ;
        const __nv_bfloat16* tW_hi = sm + s*4*TSZ + 2*TSZ;
        const __nv_bfloat16* tW_lo = sm + s*4*TSZ + 3*TSZ;

        #pragma unroll
        for (int ks=0; ks<4; ks++){
            int ko = ks*16;
            u32 Af[4][4], Whf[2][4], Wlf[2][4];
            #pragma unroll
            for (int mi=0;mi<4;mi++)
                ldsm4(Af[mi], smaddr(&tA_hi[(wm + mi*16 + ar)*SST2 + ko + ac]));
            #pragma unroll
            for (int g=0;g<2;g++)
                ldsm4(Whf[g], smaddr(&tW_hi[(wn + g*16 + brn)*SST2 + ko + bc]));
            // pass 1: Ahi * Whi
            #pragma unroll
            for (int mi=0;mi<4;mi++)
                #pragma unroll
                for (int ni=0;ni<4;ni++)
                    mma16816(acc[mi][ni], Af[mi], Whf[ni>>1][(ni&1)*2], Whf[ni>>1][(ni&1)*2+1]);
            // pass 2: Ahi * Wlo
            #pragma unroll
            for (int g=0;g<2;g++)
                ldsm4(Wlf[g], smaddr(&tW_lo[(wn + g*16 + brn)*SST2 + ko + bc]));
            #pragma unroll
            for (int mi=0;mi<4;mi++)
                #pragma unroll
                for (int ni=0;ni<4;ni++)
                    mma16816(acc[mi][ni], Af[mi], Wlf[ni>>1][(ni&1)*2], Wlf[ni>>1][(ni&1)*2+1]);
            // pass 3: Alo * Whi
            #pragma unroll
            for (int mi=0;mi<4;mi++)
                ldsm4(Af[mi], smaddr(&tA_lo[(wm + mi*16 + ar)*SST2 + ko + ac]));
            #pragma unroll
            for (int mi=0;mi<4;mi++)
                #pragma unroll
                for (int ni=0;ni<4;ni++)
                    mma16816(acc[mi][ni], Af[mi], Whf[ni>>1][(ni&1)*2], Whf[ni>>1][(ni&1)*2+1]);
        }
        __syncthreads();
    }

    // epilogue
    int er = lane>>2, ec = (lane&3)*2;
    #pragma unroll
    for (int mi=0;mi<4;mi++){
        #pragma unroll
        for (int ni=0;ni<4;ni++){
            int gm = m0 + wm + mi*16 + er;
            int gn = n0 + wn + ni*8 + ec;
            float b0 = bias ? bias[gn]   : 0.f;
            float b1 = bias ? bias[gn+1] : 0.f;
            float v0 = acc[mi][ni][0] + b0;
            float v1 = acc[mi][ni][1] + b1;
            float v2 = acc[mi][ni][2] + b0;
            float v3 = acc[mi][ni][3] + b1;
            if (act){ v0 = tanh_(v0); v1 = tanh_(v1); v2 = tanh_(v2); v3 = tanh_(v3); }
            *(float2*)&C[(size_t)gm*N + gn]     = make_float2(v0, v1);
            *(float2*)&C[(size_t)(gm+8)*N + gn] = make_float2(v2, v3);
        }
    }
}

// ------------- fp32 GEMM (head only) -------------
__global__ __launch_bounds__(256,2)
void gemm128(const float* __restrict__ A, const float* __restrict__ B,
             const float* __restrict__ bias, float* __restrict__ C,
             int M, int N, int K, int transB, int act)
{
    __shared__ float As2[16][264];
    __shared__ float Bs[16][132];
    int row0 = blockIdx.y*128, col0 = blockIdx.x*128;
    int tid = threadIdx.x;
    int tm = tid >> 4, tn = tid & 15;
    u64 acc[8][4];
    #pragma unroll
    for (int i=0;i<8;i++)
        #pragma unroll
        for (int j=0;j<4;j++) acc[i][j] = 0ull;

    for (int k0=0;k0<K;k0+=16){
        #pragma unroll
        for (int i=0;i<8;i++){
            int idx = tid + i*256;
            int r = idx >> 4, kk = idx & 15;
            int gr = row0+r, gk = k0+kk;
            float v = (gr<M && gk<K) ? A[(size_t)gr*K + gk] : 0.f;
            *(float2*)&As2[kk][2*r] = make_float2(v, v);
        }
        if (transB){
            #pragma unroll
            for (int i=0;i<8;i++){
                int idx = tid + i*256;
                int nn = idx >> 4, kk = idx & 15;
                int gk = k0+kk, gn = col0+nn;
                Bs[kk][nn] = (gk<K && gn<N) ? B[(size_t)gn*K+gk] : 0.f;
            }
        } else {
            #pragma unroll
            for (int i=0;i<8;i++){
                int idx = tid + i*256;
                int nn = idx & 127, kk = idx >> 7;
                int gk = k0+kk, gn = col0+nn;
                Bs[kk][nn] = (gk<K && gn<N) ? B[(size_t)gk*N+gn] : 0.f;
            }
        }
        __syncthreads();
        #pragma unroll
        for (int kk=0;kk<16;kk++){
            F4 b0, b1, a0, a1, a2, a3;
            b0.v = *(const float4*)&Bs[kk][tn*8];
            b1.v = *(const float4*)&Bs[kk][tn*8+4];
            a0.v = *(const float4*)&As2[kk][tm*16];
            a1.v = *(const float4*)&As2[kk][tm*16+4];
            a2.v = *(const float4*)&As2[kk][tm*16+8];
            a3.v = *(const float4*)&As2[kk][tm*16+12];
            u64 bd[4] = { b0.d[0], b0.d[1], b1.d[0], b1.d[1] };
            u64 ad[8] = { a0.d[0], a0.d[1], a1.d[0], a1.d[1],
                          a2.d[0], a2.d[1], a3.d[0], a3.d[1] };
            #pragma unroll
            for (int i=0;i<8;i++)
                #pragma unroll
                for (int j=0;j<4;j++)
                    acc[i][j] = ffma2(ad[i], bd[j], acc[i][j]);
        }
        __syncthreads();
    }
    #pragma unroll
    for (int i=0;i<8;i++){
        int gr = row0 + tm*8 + i;
        if (gr >= M) continue;
        #pragma unroll
        for (int j=0;j<4;j++){
            float2 v = unpack2(acc[i][j]);
            int gn = col0 + tn*8 + j*2;
            if (gn < N){
                float x = v.x + (bias ? bias[gn] : 0.f);
                if (act) x = tanh_(x);
                C[(size_t)gr*N + gn] = x;
            }
            if (gn+1 < N){
                float y = v.y + (bias ? bias[gn+1] : 0.f);
                if (act) y = tanh_(y);
                C[(size_t)gr*N + gn+1] = y;
            }
        }
    }
}

// ------------- LSTM scan (prefetch + double-buffered h + fused bf16 split out) --
#define HS 20
#define SCAN_SMEM ((64*G4 + 2*128*HS)*4)

__global__ __launch_bounds__(256,1)
void scan_kernel(const float* __restrict__ xwFp, const float* __restrict__ xwBp,
                 const float* __restrict__ wTF, const float* __restrict__ wTB,
                 __nv_bfloat16* __restrict__ ahi, __nv_bfloat16* __restrict__ alo,
                 float* __restrict__ hout)
{
    extern __shared__ float smf[];
    float* Ws  = smf;
    float* hsA = smf + 64*G4;
    float* hsB = hsA + 128*HS;
    int tid = threadIdx.x;
    int dir = blockIdx.x >> 6;
    int grp = blockIdx.x & 63;
    int b0 = grp*8;
    const float* xw = dir ? xwBp : xwFp;
    const float* wD = dir ? wTB : wTF;
    int hOff = dir*128;
    int h  = tid & 127;
    int rg = tid >> 7;

    for (int i=tid;i<64*G4;i+=256) Ws[i] = wD[i];
    for (int i=tid;i<2*128*HS;i+=256) hsA[i] = 0.f;
    float cst[4] = {0.f,0.f,0.f,0.f};

    const float* xp[4];
    __nv_bfloat16 *ahp[4], *alp[4];
    float* hop[4];
    #pragma unroll
    for (int r=0;r<4;r++){
        size_t rowbase = (size_t)(b0+4*rg+r)*Tt;
        xp[r]  = xw  + rowbase*G4 + 4*h;
        ahp[r] = ahi + rowbase*256 + hOff + h;
        alp[r] = alo + rowbase*256 + hOff + h;
        hop[r] = hout ? (hout + rowbase*256 + hOff + h) : (float*)0;
    }
    __syncthreads();

    int t0 = dir ? (Tt-1) : 0;
    F4 xvc[4];
    #pragma unroll
    for (int r=0;r<4;r++) xvc[r].v = *(const float4*)&xp[r][(size_t)t0*G4];

    for (int s=0;s<Tt;s++){
        int t = dir ? (Tt-1-s) : s;
        float* hsR = (s&1) ? hsB : hsA;
        float* hsW = (s&1) ? hsA : hsB;

        F4 xvn[4];
        if (s+1 < Tt){
            int tn_ = dir ? (Tt-2-s) : (s+1);
            #pragma unroll
            for (int r=0;r<4;r++) xvn[r].v = *(const float4*)&xp[r][(size_t)tn_*G4];
        }

        u64 aIF[4] = {0,0,0,0}, aGO[4] = {0,0,0,0};
        #pragma unroll 8
        for (int k=0;k<64;k++){
            F4 w;  w.v  = *(const float4*)&Ws[k*G4 + 4*h];
            F4 p0; p0.v = *(const float4*)&hsR[k*HS + 8*rg];
            F4 p1; p1.v = *(const float4*)&hsR[k*HS + 8*rg + 4];
            aIF[0]=ffma2(p0.d[0], w.d[0], aIF[0]); aGO[0]=ffma2(p0.d[0], w.d[1], aGO[0]);
            aIF[1]=ffma2(p0.d[1], w.d[0], aIF[1]); aGO[1]=ffma2(p0.d[1], w.d[1], aGO[1]);
            aIF[2]=ffma2(p1.d[0], w.d[0], aIF[2]); aGO[2]=ffma2(p1.d[0], w.d[1], aGO[2]);
            aIF[3]=ffma2(p1.d[1], w.d[0], aIF[3]); aGO[3]=ffma2(p1.d[1], w.d[1], aGO[3]);
        }
        for (int kb=64;kb<128;kb+=8){
            F4 w[8];
            #pragma unroll
            for (int j=0;j<8;j++) w[j].v = *(const float4*)&wD[(size_t)(kb+j)*G4 + 4*h];
            #pragma unroll
            for (int j=0;j<8;j++){
                int k = kb+j;
                F4 p0; p0.v = *(const float4*)&hsR[k*HS + 8*rg];
                F4 p1; p1.v = *(const float4*)&hsR[k*HS + 8*rg + 4];
                aIF[0]=ffma2(p0.d[0], w[j].d[0], aIF[0]); aGO[0]=ffma2(p0.d[0], w[j].d[1], aGO[0]);
                aIF[1]=ffma2(p0.d[1], w[j].d[0], aIF[1]); aGO[1]=ffma2(p0.d[1], w[j].d[1], aGO[1]);
                aIF[2]=ffma2(p1.d[0], w[j].d[0], aIF[2]); aGO[2]=ffma2(p1.d[0], w[j].d[1], aGO[2]);
                aIF[3]=ffma2(p1.d[1], w[j].d[0], aIF[3]); aGO[3]=ffma2(p1.d[1], w[j].d[1], aGO[3]);
            }
        }
        float hnew[4];
        #pragma unroll
        for (int r=0;r<4;r++){
            float2 v1 = unpack2(aIF[r]);
            float2 v2 = unpack2(aGO[r]);
            float gi = v1.x + xvc[r].f[0];
            float gf = v1.y + xvc[r].f[1];
            float gg = v2.x + xvc[r].f[2];
            float go = v2.y + xvc[r].f[3];
            float cc = sigf(gf)*cst[r] + sigf(gi)*tanh_(gg);
            cst[r] = cc;
            hnew[r] = sigf(go)*tanh_(cc);
        }
        size_t tOff = (size_t)t*256;
        #pragma unroll
        for (int r=0;r<4;r++){
            float v = hnew[r];
            *(float2*)&hsW[h*HS + 2*(4*rg+r)] = make_float2(v, v);
            __nv_bfloat16 hh = __float2bfloat16(v);
            ahp[r][tOff] = hh;
            alp[r][tOff] = __float2bfloat16(v - __bfloat162float(hh));
            if (hop[r]) hop[r][tOff] = v;
        }
        __syncthreads();
        #pragma unroll
        for (int r=0;r<4;r++) xvc[r] = xvn[r];
    }
}

// ------------- attention -------------
__global__ __launch_bounds__(256,1)
void att_kernel(const float* __restrict__ u, const float* __restrict__ h1,
                const float* __restrict__ v, float* __restrict__ att)
{
    __shared__ float sa[Tt];
    __shared__ float red[256];
    __shared__ float vs[256];
    int b = blockIdx.x, tid = threadIdx.x;
    int wd = tid>>5, ln = tid&31;
    vs[tid] = v[tid];
    __syncthreads();
    for (int t = wd; t < Tt; t += 8){
        const float* ur = u + ((size_t)b*Tt + t)*256;
        float s = 0.f;
        #pragma unroll
        for (int j=0;j<8;j++) s += ur[ln+32*j]*vs[ln+32*j];
        #pragma unroll
        for (int o=16;o;o>>=1) s += __shfl_xor_sync(0xFFFFFFFFu, s, o);
        if (ln==0) sa[t] = s;
    }
    __syncthreads();
    float m = -3.4e38f;
    for (int t=tid;t<Tt;t+=256) m = fmaxf(m, sa[t]);
    red[tid] = m; __syncthreads();
    for (int off=128; off>0; off>>=1){ if (tid<off) red[tid]=fmaxf(red[tid],red[tid+off]); __syncthreads(); }
    float mx = red[0]; __syncthreads();
    float sum = 0.f;
    for (int t=tid;t<Tt;t+=256){ float e = __expf(sa[t]-mx); sa[t]=e; sum+=e; }
    red[tid] = sum; __syncthreads();
    for (int off=128; off>0; off>>=1){ if (tid<off) red[tid]+=red[tid+off]; __syncthreads(); }
    float inv = __fdividef(1.f, red[0]);
    __syncthreads();
    float acc = 0.f;
    const float* hb = h1 + (size_t)b*Tt*256 + tid;
    #pragma unroll 4
    for (int t=0;t<Tt;t++) acc += hb[(size_t)t*256] * sa[t];
    att[b*256 + tid] = acc * inv;
}

// ------------- launch -------------
extern "C" void kernel_launch(void* const* d_in, const int* in_sizes, int n_in,
                              void* d_out, int out_size)
{
    const float* X      = (const float*)d_in[0];
    const float* wih0f  = (const float*)d_in[1];
    const float* whh0f  = (const float*)d_in[2];
    const float* bih0f  = (const float*)d_in[3];
    const float* bhh0f  = (const float*)d_in[4];
    const float* wih0b  = (const float*)d_in[5];
    const float* whh0b  = (const float*)d_in[6];
    const float* bih0b  = (const float*)d_in[7];
    const float* bhh0b  = (const float*)d_in[8];
    const float* wih1f  = (const float*)d_in[9];
    const float* whh1f  = (const float*)d_in[10];
    const float* bih1f  = (const float*)d_in[11];
    const float* bhh1f  = (const float*)d_in[12];
    const float* wih1b  = (const float*)d_in[13];
    const float* whh1b  = (const float*)d_in[14];
    const float* bih1b  = (const float*)d_in[15];
    const float* bhh1b  = (const float*)d_in[16];
    const float* attW   = (const float*)d_in[17];
    const float* attV   = (const float*)d_in[18];
    const float* headW  = (const float*)d_in[19];
    const float* headB  = (const float*)d_in[20];
    float* out = (float*)d_out;

    cudaFuncSetAttribute(scan_kernel, cudaFuncAttributeMaxDynamicSharedMemorySize, SCAN_SMEM);
    cudaFuncSetAttribute(mma_gemm,    cudaFuncAttributeMaxDynamicSharedMemorySize, MMA_SMEM);

    float *xwF, *xwB, *h1, *wT, *wi0, *wi1, *bsum, *att;
    __nv_bfloat16 *ahi, *alo, *whi, *wlo;
    cudaGetSymbolAddress((void**)&xwF, g_xwF);
    cudaGetSymbolAddress((void**)&xwB, g_xwB);
    cudaGetSymbolAddress((void**)&h1,  g_h1);
    cudaGetSymbolAddress((void**)&wT,  g_wT);
    cudaGetSymbolAddress((void**)&wi0, g_wih0);
    cudaGetSymbolAddress((void**)&wi1, g_wih1);
    cudaGetSymbolAddress((void**)&bsum,g_bsum);
    cudaGetSymbolAddress((void**)&att, g_att);
    cudaGetSymbolAddress((void**)&ahi, g_ahi);
    cudaGetSymbolAddress((void**)&alo, g_alo);
    cudaGetSymbolAddress((void**)&whi, g_whi);
    cudaGetSymbolAddress((void**)&wlo, g_wlo);

    // prep: reorder weights into gate-interleaved layouts, fold biases
    reorder_wih<<<(G4*Cc+255)/256, 256>>>(wih0f, wi0,            Cc);
    reorder_wih<<<(G4*Cc+255)/256, 256>>>(wih0b, wi0 + G4*Cc,    Cc);
    reorder_wih<<<(G4*256+255)/256,256>>>(wih1f, wi1,            256);
    reorder_wih<<<(G4*256+255)/256,256>>>(wih1b, wi1 + G4*256,   256);
    reorder_whh<<<(Hh*G4+255)/256, 256>>>(whh0f, wT + 0*Hh*G4);
    reorder_whh<<<(Hh*G4+255)/256, 256>>>(whh0b, wT + 1*Hh*G4);
    reorder_whh<<<(Hh*G4+255)/256, 256>>>(whh1f, wT + 2*Hh*G4);
    reorder_whh<<<(Hh*G4+255)/256, 256>>>(whh1b, wT + 3*Hh*G4);
    fold_b<<<2,256>>>(bih0f, bhh0f, bsum + 0*G4);
    fold_b<<<2,256>>>(bih0b, bhh0b, bsum + 1*G4);
    fold_b<<<2,256>>>(bih1f, bhh1f, bsum + 2*G4);
    fold_b<<<2,256>>>(bih1b, bhh1b, bsum + 3*G4);

    // weight bf16 splits
    conv_split<<<(512*KP0+255)/256,256>>>(wi0,          whi+WOFF0F, wlo+WOFF0F, 512*KP0, Cc, KP0);
    conv_split<<<(512*KP0+255)/256,256>>>(wi0 + G4*Cc,  whi+WOFF0B, wlo+WOFF0B, 512*KP0, Cc, KP0);
    conv_split<<<(512*256+255)/256,256>>>(wi1,          whi+WOFF1F, wlo+WOFF1F, 512*256, 256, 256);
    conv_split<<<(512*256+255)/256,256>>>(wi1 + G4*256, whi+WOFF1B, wlo+WOFF1B, 512*256, 256, 256);
    conv_splitT<<<(256*256+255)/256,256>>>(attW, whi+WOFFATT, wlo+WOFFATT, 256, 256, 256);

    // x -> transposed split bf16 A (layer 0 input), zero-padded to KP0
    transpose_split<<<dim3((Tt+31)/32,(KP0+31)/32,Bsz), dim3(32,8)>>>(X, ahi, alo);

    // layer 0
    dim3 g0(4, BT/128);
    mma_gemm<<<g0,256,MMA_SMEM>>>(ahi, alo, whi+WOFF0F, wlo+WOFF0F, bsum + 0*G4, xwF, BT, G4, KP0, 0);
    mma_gemm<<<g0,256,MMA_SMEM>>>(ahi, alo, whi+WOFF0B, wlo+WOFF0B, bsum + 1*G4, xwB, BT, G4, KP0, 0);
    scan_kernel<<<128,256,SCAN_SMEM>>>(xwF, xwB, wT + 0*Hh*G4, wT + 1*Hh*G4, ahi, alo, (float*)0);

    // layer 1 (A = h0 splits written by scan0, K=256)
    mma_gemm<<<g0,256,MMA_SMEM>>>(ahi, alo, whi+WOFF1F, wlo+WOFF1F, bsum + 2*G4, xwF, BT, G4, 256, 0);
    mma_gemm<<<g0,256,MMA_SMEM>>>(ahi, alo, whi+WOFF1B, wlo+WOFF1B, bsum + 3*G4, xwB, BT, G4, 256, 0);
    scan_kernel<<<128,256,SCAN_SMEM>>>(xwF, xwB, wT + 2*Hh*G4, wT + 3*Hh*G4, ahi, alo, h1);

    // attention u = tanh(h1 @ att_W)  (A = h1 splits from scan1)
    mma_gemm<<<dim3(2, BT/128),256,MMA_SMEM>>>(ahi, alo, whi+WOFFATT, wlo+WOFFATT, (const float*)0, xwF, BT, 256, 256, 1);
    att_kernel<<<Bsz,256>>>(xwF, h1, attV, att);
    // head (fp32)
    gemm128<<<dim3((NCLS+127)/128,(Bsz+127)/128),256>>>(att, headW, headB, out, Bsz, NCLS, 256, 1, 0);
}

// round 11
// speedup vs baseline: 1.7511x; 1.0537x over previous
#include <cuda_runtime.h>
#include <cuda_bf16.h>
#include <cstdint>

#define Bsz 512
#define Cc  271
#define Tt  281
#define Hh  128
#define NCLS 1854
#define BT  (Bsz*Tt)      /* 143872 */
#define G4  512
#define KP0 320           /* padded K for layer0 (multiple of 64) */

typedef unsigned long long u64;
typedef unsigned int u32;

union F4 { float4 v; float f[4]; u64 d[2]; };

__device__ __forceinline__ u64 ffma2(u64 a, u64 b, u64 c){
    u64 d; asm("fma.rn.f32x2 %0, %1, %2, %3;" : "=l"(d) : "l"(a), "l"(b), "l"(c)); return d;
}
__device__ __forceinline__ float2 unpack2(u64 d){
    float lo, hi; asm("mov.b64 {%0, %1}, %2;" : "=f"(lo), "=f"(hi) : "l"(d));
    return make_float2(lo, hi);
}
__device__ __forceinline__ float sigf(float x){ return __fdividef(1.f, 1.f + __expf(-x)); }
__device__ __forceinline__ float tanh_(float x){ return 1.f - __fdividef(2.f, __expf(2.f*x) + 1.f); }

// ------------- device scratch -------------
__device__ float g_xwF[(size_t)BT*G4];
__device__ float g_xwB[(size_t)BT*G4];
__device__ float g_h1 [(size_t)BT*2*Hh];
__device__ float g_wT [4*Hh*G4];          // 4x [128][512] gate-interleaved W_hh^T
__device__ float g_bsum[4*G4];
__device__ float g_att[Bsz*2*Hh];
// bf16 split buffers (A operand: x for layer0, h for layer1/att)
__device__ __nv_bfloat16 g_ahi[(size_t)BT*KP0];
__device__ __nv_bfloat16 g_alo[(size_t)BT*KP0];
#define WOFF0F 0
#define WOFF0B (512*KP0)
#define WOFF1F (2*512*KP0)
#define WOFF1B (2*512*KP0 + 512*256)
#define WOFFATT (2*512*KP0 + 2*512*256)
#define WTOT (WOFFATT + 256*256)
__device__ __nv_bfloat16 g_whi[WTOT];
__device__ __nv_bfloat16 g_wlo[WTOT];

__device__ __forceinline__ int oldrow(int n){ return (n&3)*128 + (n>>2); }

// ------------- fused prep kernels -------------
// w_ih reorder (gate-interleave) + bf16 hi/lo split + K padding, both directions
__global__ void wsplit(const float* __restrict__ srcF, const float* __restrict__ srcB,
                       __nv_bfloat16* __restrict__ hiF, __nv_bfloat16* __restrict__ loF,
                       __nv_bfloat16* __restrict__ hiB, __nv_bfloat16* __restrict__ loB,
                       int Ks, int Kp){
    int i = blockIdx.x*256 + threadIdx.x;
    if (i >= 2*G4*Kp) return;
    int half = i / (G4*Kp);
    int j = i - half*(G4*Kp);
    int n = j / Kp, k = j - n*Kp;
    const float* s = half ? srcB : srcF;
    float v = (k < Ks) ? s[oldrow(n)*Ks + k] : 0.f;
    __nv_bfloat16 h = __float2bfloat16(v);
    (half ? hiB : hiF)[j] = h;
    (half ? loB : loF)[j] = __float2bfloat16(v - __bfloat162float(h));
}
// attention W split (transposed: dst row n = attW[:,n])
__global__ void conv_splitT(const float* __restrict__ src, __nv_bfloat16* __restrict__ hi,
                            __nv_bfloat16* __restrict__ lo, int N, int Ks, int Kp){
    int i = blockIdx.x*256 + threadIdx.x;
    if (i >= N*Kp) return;
    int n = i / Kp, k = i - n*Kp;
    float v = (k < Ks) ? src[(size_t)k*N + n] : 0.f;
    __nv_bfloat16 h = __float2bfloat16(v);
    hi[i] = h;
    lo[i] = __float2bfloat16(v - __bfloat162float(h));
}
// all 4 W_hh reorders + 4 bias folds in one launch
__global__ void whh_fold(const float* __restrict__ w0, const float* __restrict__ w1,
                         const float* __restrict__ w2, const float* __restrict__ w3,
                         const float* __restrict__ bi0, const float* __restrict__ bh0,
                         const float* __restrict__ bi1, const float* __restrict__ bh1,
                         const float* __restrict__ bi2, const float* __restrict__ bh2,
                         const float* __restrict__ bi3, const float* __restrict__ bh3,
                         float* __restrict__ wT, float* __restrict__ bsum){
    int i = blockIdx.x*256 + threadIdx.x;
    if (i < 4*Hh*G4){
        int m = i / (Hh*G4);
        int r = i - m*(Hh*G4);
        int k = r >> 9, n = r & 511;
        const float* w = (m==0)?w0:(m==1)?w1:(m==2)?w2:w3;
        wT[i] = w[oldrow(n)*Hh + k];
    } else if (i < 4*Hh*G4 + 4*G4){
        int j = i - 4*Hh*G4;
        int m = j / G4, n = j - m*G4;
        const float* bi = (m==0)?bi0:(m==1)?bi1:(m==2)?bi2:bi3;
        const float* bh = (m==0)?bh0:(m==1)?bh1:(m==2)?bh2:bh3;
        int o = oldrow(n);
        bsum[j] = bi[o] + bh[o];
    }
}

// ------------- transpose X[B,C,T] -> split bf16 A[B*T, KP0] -------------
__global__ void transpose_split(const float* __restrict__ X,
                                __nv_bfloat16* __restrict__ hi,
                                __nv_bfloat16* __restrict__ lo){
    __shared__ float tile[32][33];
    int b = blockIdx.z;
    int t0 = blockIdx.x*32, c0 = blockIdx.y*32;
    int tx = threadIdx.x, ty = threadIdx.y;
    const float* Xb = X + (size_t)b*Cc*Tt;
    #pragma unroll
    for (int i=0;i<32;i+=8){
        int c = c0+ty+i, t = t0+tx;
        tile[ty+i][tx] = (c<Cc && t<Tt) ? Xb[(size_t)c*Tt + t] : 0.f;
    }
    __syncthreads();
    #pragma unroll
    for (int i=0;i<32;i+=8){
        int t = t0+ty+i, c = c0+tx;
        if (t<Tt){
            float v = tile[tx][ty+i];
            __nv_bfloat16 h = __float2bfloat16(v);
            size_t idx = ((size_t)b*Tt + t)*KP0 + c;
            hi[idx] = h;
            lo[idx] = __float2bfloat16(v - __bfloat162float(h));
        }
    }
}

// ------------- tensor-core GEMM, split-bf16 (3 passes), 64-wide K chunks -------
#define SST2 72                  /* smem row stride in halves (64 data + 8 pad) */
#define TSZ  (128*SST2)          /* halves per tile */
#define MMA_SMEM (2*4*TSZ*2)     /* bytes: 2 stages x 4 tiles = 147456 */
__device__ __forceinline__ u32 smaddr(const void* p){ return (u32)__cvta_generic_to_shared(p); }
__device__ __forceinline__ void cpasync16(u32 s, const void* g){
    asm volatile("cp.async.cg.shared.global [%0], [%1], 16;" :: "r"(s), "l"(g));
}
__device__ __forceinline__ void ldsm4(u32* r, u32 a){
    asm volatile("ldmatrix.sync.aligned.m8n8.x4.shared.b16 {%0,%1,%2,%3}, [%4];"
        : "=r"(r[0]),"=r"(r[1]),"=r"(r[2]),"=r"(r[3]) : "r"(a));
}
__device__ __forceinline__ void mma16816(float* d, const u32* a, u32 b0, u32 b1){
    asm volatile("mma.sync.aligned.m16n8k16.row.col.f32.bf16.bf16.f32 "
        "{%0,%1,%2,%3}, {%4,%5,%6,%7}, {%8,%9}, {%0,%1,%2,%3};"
        : "+f"(d[0]),"+f"(d[1]),"+f"(d[2]),"+f"(d[3])
        : "r"(a[0]),"r"(a[1]),"r"(a[2]),"r"(a[3]), "r"(b0),"r"(b1));
}

__global__ __launch_bounds__(256,1)
void mma_gemm(const __nv_bfloat16* __restrict__ Ahi, const __nv_bfloat16* __restrict__ Alo,
              const __nv_bfloat16* __restrict__ Whi, const __nv_bfloat16* __restrict__ Wlo,
              const float* __restrict__ bias, float* __restrict__ C,
              int M, int N, int Kp, int act)
{
    extern __shared__ __align__(16) __nv_bfloat16 sm[];   // [2][4][TSZ]
    int tid = threadIdx.x;
    int wid = tid>>5, lane = tid&31;
    int m0 = blockIdx.y*128, n0 = blockIdx.x*128;
    int wm = (wid>>2)*64, wn = (wid&3)*32;

    float acc[4][4][4];
    #pragma unroll
    for (int i=0;i<4;i++)
      #pragma unroll
      for (int j=0;j<4;j++)
        #pragma unroll
        for (int q=0;q<4;q++) acc[i][j][q] = 0.f;

    const __nv_bfloat16* gsrc[4];
    gsrc[0] = Ahi + (size_t)m0*Kp;
    gsrc[1] = Alo + (size_t)m0*Kp;
    gsrc[2] = Whi + (size_t)n0*Kp;
    gsrc[3] = Wlo + (size_t)n0*Kp;

    int NC = Kp >> 6;                       // 64-wide chunks

    {   // prologue: chunk 0 -> stage 0
        #pragma unroll
        for (int t=0;t<4;t++){
            #pragma unroll
            for (int i=0;i<4;i++){
                int u = tid + i*256;
                int row = u>>3, seg = u&7;
                cpasync16(smaddr(&sm[t*TSZ + row*SST2 + seg*8]),
                          gsrc[t] + (size_t)row*Kp + seg*8);
            }
        }
        asm volatile("cp.async.commit_group;" ::: "memory");
    }

    int ar = lane & 15;
    int ac = (lane >> 4) * 8;
    int brn = (lane & 7) + ((lane & 16) ? 8 : 0);
    int bc  = (lane & 8) ? 8 : 0;

    for (int c=0;c<NC;c++){
        if (c+1 < NC){
            int k0 = (c+1)*64, s = (c+1)&1;
            #pragma unroll
            for (int t=0;t<4;t++){
                #pragma unroll
                for (int i=0;i<4;i++){
                    int u = tid + i*256;
                    int row = u>>3, seg = u&7;
                    cpasync16(smaddr(&sm[s*4*TSZ + t*TSZ + row*SST2 + seg*8]),
                              gsrc[t] + (size_t)row*Kp + k0 + seg*8);
                }
            }
            asm volatile("cp.async.commit_group;" ::: "memory");
            asm volatile("cp.async.wait_group 1;" ::: "memory");
        } else {
            asm volatile("cp.async.wait_group 0;" ::: "memory");
        }
        __syncthreads();
        int s = c & 1;
        const __nv_bfloat16* tA_hi = sm + s*4*TSZ + 0*TSZ;
        const __nv_bfloat16* tA_lo = sm + s*4*TSZ + 1*TSZ;
        const __nv_bfloat16* tW_hi = sm + s*4*TSZ + 2*TSZ;
        const __nv_bfloat16* tW_lo = sm + s*4*TSZ + 3*TSZ;

        #pragma unroll
        for (int ks=0; ks<4; ks++){
            int ko = ks*16;
            u32 Af[4][4], Whf[2][4], Wlf[2][4];
            #pragma unroll
            for (int mi=0;mi<4;mi++)
                ldsm4(Af[mi], smaddr(&tA_hi[(wm + mi*16 + ar)*SST2 + ko + ac]));
            #pragma unroll
            for (int g=0;g<2;g++)
                ldsm4(Whf[g], smaddr(&tW_hi[(wn + g*16 + brn)*SST2 + ko + bc]));
            // pass 1: Ahi * Whi
            #pragma unroll
            for (int mi=0;mi<4;mi++)
                #pragma unroll
                for (int ni=0;ni<4;ni++)
                    mma16816(acc[mi][ni], Af[mi], Whf[ni>>1][(ni&1)*2], Whf[ni>>1][(ni&1)*2+1]);
            // pass 2: Ahi * Wlo
            #pragma unroll
            for (int g=0;g<2;g++)
                ldsm4(Wlf[g], smaddr(&tW_lo[(wn + g*16 + brn)*SST2 + ko + bc]));
            #pragma unroll
            for (int mi=0;mi<4;mi++)
                #pragma unroll
                for (int ni=0;ni<4;ni++)
                    mma16816(acc[mi][ni], Af[mi], Wlf[ni>>1][(ni&1)*2], Wlf[ni>>1][(ni&1)*2+1]);
            // pass 3: Alo * Whi
            #pragma unroll
            for (int mi=0;mi<4;mi++)
                ldsm4(Af[mi], smaddr(&tA_lo[(wm + mi*16 + ar)*SST2 + ko + ac]));
            #pragma unroll
            for (int mi=0;mi<4;mi++)
                #pragma unroll
                for (int ni=0;ni<4;ni++)
                    mma16816(acc[mi][ni], Af[mi], Whf[ni>>1][(ni&1)*2], Whf[ni>>1][(ni&1)*2+1]);
        }
        __syncthreads();
    }

    // epilogue
    int er = lane>>2, ec = (lane&3)*2;
    #pragma unroll
    for (int mi=0;mi<4;mi++){
        #pragma unroll
        for (int ni=0;ni<4;ni++){
            int gm = m0 + wm + mi*16 + er;
            int gn = n0 + wn + ni*8 + ec;
            float b0 = bias ? bias[gn]   : 0.f;
            float b1 = bias ? bias[gn+1] : 0.f;
            float v0 = acc[mi][ni][0] + b0;
            float v1 = acc[mi][ni][1] + b1;
            float v2 = acc[mi][ni][2] + b0;
            float v3 = acc[mi][ni][3] + b1;
            if (act){ v0 = tanh_(v0); v1 = tanh_(v1); v2 = tanh_(v2); v3 = tanh_(v3); }
            *(float2*)&C[(size_t)gm*N + gn]     = make_float2(v0, v1);
            *(float2*)&C[(size_t)(gm+8)*N + gn] = make_float2(v2, v3);
        }
    }
}

// ------------- fp32 GEMM (head only) -------------
__global__ __launch_bounds__(256,2)
void gemm128(const float* __restrict__ A, const float* __restrict__ B,
             const float* __restrict__ bias, float* __restrict__ C,
             int M, int N, int K, int transB, int act)
{
    __shared__ float As2[16][264];
    __shared__ float Bs[16][132];
    int row0 = blockIdx.y*128, col0 = blockIdx.x*128;
    int tid = threadIdx.x;
    int tm = tid >> 4, tn = tid & 15;
    u64 acc[8][4];
    #pragma unroll
    for (int i=0;i<8;i++)
        #pragma unroll
        for (int j=0;j<4;j++) acc[i][j] = 0ull;

    for (int k0=0;k0<K;k0+=16){
        #pragma unroll
        for (int i=0;i<8;i++){
            int idx = tid + i*256;
            int r = idx >> 4, kk = idx & 15;
            int gr = row0+r, gk = k0+kk;
            float v = (gr<M && gk<K) ? A[(size_t)gr*K + gk] : 0.f;
            *(float2*)&As2[kk][2*r] = make_float2(v, v);
        }
        if (transB){
            #pragma unroll
            for (int i=0;i<8;i++){
                int idx = tid + i*256;
                int nn = idx >> 4, kk = idx & 15;
                int gk = k0+kk, gn = col0+nn;
                Bs[kk][nn] = (gk<K && gn<N) ? B[(size_t)gn*K+gk] : 0.f;
            }
        } else {
            #pragma unroll
            for (int i=0;i<8;i++){
                int idx = tid + i*256;
                int nn = idx & 127, kk = idx >> 7;
                int gk = k0+kk, gn = col0+nn;
                Bs[kk][nn] = (gk<K && gn<N) ? B[(size_t)gk*N+gn] : 0.f;
            }
        }
        __syncthreads();
        #pragma unroll
        for (int kk=0;kk<16;kk++){
            F4 b0, b1, a0, a1, a2, a3;
            b0.v = *(const float4*)&Bs[kk][tn*8];
            b1.v = *(const float4*)&Bs[kk][tn*8+4];
            a0.v = *(const float4*)&As2[kk][tm*16];
            a1.v = *(const float4*)&As2[kk][tm*16+4];
            a2.v = *(const float4*)&As2[kk][tm*16+8];
            a3.v = *(const float4*)&As2[kk][tm*16+12];
            u64 bd[4] = { b0.d[0], b0.d[1], b1.d[0], b1.d[1] };
            u64 ad[8] = { a0.d[0], a0.d[1], a1.d[0], a1.d[1],
                          a2.d[0], a2.d[1], a3.d[0], a3.d[1] };
            #pragma unroll
            for (int i=0;i<8;i++)
                #pragma unroll
                for (int j=0;j<4;j++)
                    acc[i][j] = ffma2(ad[i], bd[j], acc[i][j]);
        }
        __syncthreads();
    }
    #pragma unroll
    for (int i=0;i<8;i++){
        int gr = row0 + tm*8 + i;
        if (gr >= M) continue;
        #pragma unroll
        for (int j=0;j<4;j++){
            float2 v = unpack2(acc[i][j]);
            int gn = col0 + tn*8 + j*2;
            if (gn < N){
                float x = v.x + (bias ? bias[gn] : 0.f);
                if (act) x = tanh_(x);
                C[(size_t)gr*N + gn] = x;
            }
            if (gn+1 < N){
                float y = v.y + (bias ? bias[gn+1] : 0.f);
                if (act) y = tanh_(y);
                C[(size_t)gr*N + gn+1] = y;
            }
        }
    }
}

// ------------- LSTM scan: 128 threads, 8 rows/thread (W read once per step) ----
#define HS 20
#define SCAN_SMEM ((64*G4 + 2*128*HS)*4)
#define ROWX ((size_t)Tt*G4)
#define ROWH ((size_t)Tt*256)

__global__ __launch_bounds__(128,1)
void scan_kernel(const float* __restrict__ xwFp, const float* __restrict__ xwBp,
                 const float* __restrict__ wTF, const float* __restrict__ wTB,
                 __nv_bfloat16* __restrict__ ahi, __nv_bfloat16* __restrict__ alo,
                 float* __restrict__ hout)
{
    extern __shared__ float smf[];
    float* Ws  = smf;                 // 64 x 512
    float* hsA = smf + 64*G4;         // 128 x HS (dup pairs of 8 rows)
    float* hsB = hsA + 128*HS;
    int h = threadIdx.x;              // 0..127
    int dir = blockIdx.x >> 6;
    int grp = blockIdx.x & 63;
    int b0 = grp*8;
    const float* xw = dir ? xwBp : xwFp;
    const float* wD = dir ? wTB : wTF;
    int hOff = dir*128;

    for (int i=h;i<64*G4;i+=128) Ws[i] = wD[i];
    for (int i=h;i<2*128*HS;i+=128) hsA[i] = 0.f;
    float cst[8] = {0.f,0.f,0.f,0.f,0.f,0.f,0.f,0.f};

    const float* xb = xw + (size_t)b0*ROWX + 4*h;
    __nv_bfloat16* ahb = ahi + (size_t)b0*ROWH + hOff + h;
    __nv_bfloat16* alb = alo + (size_t)b0*ROWH + hOff + h;
    float* hob = hout ? (hout + (size_t)b0*ROWH + hOff + h) : (float*)0;
    __syncthreads();

    for (int s=0;s<Tt;s++){
        int t = dir ? (Tt-1-s) : s;
        float* hsR = (s&1) ? hsB : hsA;
        float* hsW = (s&1) ? hsA : hsB;

        // issue xv loads early; consumed after the matvec (latency hidden)
        F4 xv[8];
        size_t tX = (size_t)t*G4;
        #pragma unroll
        for (int r=0;r<8;r++) xv[r].v = *(const float4*)&xb[r*ROWX + tX];

        u64 aIF[8] = {0,0,0,0,0,0,0,0}, aGO[8] = {0,0,0,0,0,0,0,0};
        // SMEM half of W
        #pragma unroll 4
        for (int k=0;k<64;k++){
            F4 w;  w.v  = *(const float4*)&Ws[k*G4 + 4*h];
            F4 p0; p0.v = *(const float4*)&hsR[k*HS];
            F4 p1; p1.v = *(const float4*)&hsR[k*HS + 4];
            F4 p2; p2.v = *(const float4*)&hsR[k*HS + 8];
            F4 p3; p3.v = *(const float4*)&hsR[k*HS + 12];
            aIF[0]=ffma2(p0.d[0], w.d[0], aIF[0]); aGO[0]=ffma2(p0.d[0], w.d[1], aGO[0]);
            aIF[1]=ffma2(p0.d[1], w.d[0], aIF[1]); aGO[1]=ffma2(p0.d[1], w.d[1], aGO[1]);
            aIF[2]=ffma2(p1.d[0], w.d[0], aIF[2]); aGO[2]=ffma2(p1.d[0], w.d[1], aGO[2]);
            aIF[3]=ffma2(p1.d[1], w.d[0], aIF[3]); aGO[3]=ffma2(p1.d[1], w.d[1], aGO[3]);
            aIF[4]=ffma2(p2.d[0], w.d[0], aIF[4]); aGO[4]=ffma2(p2.d[0], w.d[1], aGO[4]);
            aIF[5]=ffma2(p2.d[1], w.d[0], aIF[5]); aGO[5]=ffma2(p2.d[1], w.d[1], aGO[5]);
            aIF[6]=ffma2(p3.d[0], w.d[0], aIF[6]); aGO[6]=ffma2(p3.d[0], w.d[1], aGO[6]);
            aIF[7]=ffma2(p3.d[1], w.d[0], aIF[7]); aGO[7]=ffma2(p3.d[1], w.d[1], aGO[7]);
        }
        // global (L2) half of W, batch-prefetched
        for (int kb=64;kb<128;kb+=8){
            F4 w[8];
            #pragma unroll
            for (int j=0;j<8;j++) w[j].v = *(const float4*)&wD[(size_t)(kb+j)*G4 + 4*h];
            #pragma unroll
            for (int j=0;j<8;j++){
                int k = kb+j;
                F4 p0; p0.v = *(const float4*)&hsR[k*HS];
                F4 p1; p1.v = *(const float4*)&hsR[k*HS + 4];
                F4 p2; p2.v = *(const float4*)&hsR[k*HS + 8];
                F4 p3; p3.v = *(const float4*)&hsR[k*HS + 12];
                aIF[0]=ffma2(p0.d[0], w[j].d[0], aIF[0]); aGO[0]=ffma2(p0.d[0], w[j].d[1], aGO[0]);
                aIF[1]=ffma2(p0.d[1], w[j].d[0], aIF[1]); aGO[1]=ffma2(p0.d[1], w[j].d[1], aGO[1]);
                aIF[2]=ffma2(p1.d[0], w[j].d[0], aIF[2]); aGO[2]=ffma2(p1.d[0], w[j].d[1], aGO[2]);
                aIF[3]=ffma2(p1.d[1], w[j].d[0], aIF[3]); aGO[3]=ffma2(p1.d[1], w[j].d[1], aGO[3]);
                aIF[4]=ffma2(p2.d[0], w[j].d[0], aIF[4]); aGO[4]=ffma2(p2.d[0], w[j].d[1], aGO[4]);
                aIF[5]=ffma2(p2.d[1], w[j].d[0], aIF[5]); aGO[5]=ffma2(p2.d[1], w[j].d[1], aGO[5]);
                aIF[6]=ffma2(p3.d[0], w[j].d[0], aIF[6]); aGO[6]=ffma2(p3.d[0], w[j].d[1], aGO[6]);
                aIF[7]=ffma2(p3.d[1], w[j].d[0], aIF[7]); aGO[7]=ffma2(p3.d[1], w[j].d[1], aGO[7]);
            }
        }
        size_t tH = (size_t)t*256;
        #pragma unroll
        for (int r=0;r<8;r++){
            float2 v1 = unpack2(aIF[r]);
            float2 v2 = unpack2(aGO[r]);
            float gi = v1.x + xv[r].f[0];
            float gf = v1.y + xv[r].f[1];
            float gg = v2.x + xv[r].f[2];
            float go = v2.y + xv[r].f[3];
            float cc = sigf(gf)*cst[r] + sigf(gi)*tanh_(gg);
            cst[r] = cc;
            float hn = sigf(go)*tanh_(cc);
            *(float2*)&hsW[h*HS + 2*r] = make_float2(hn, hn);
            __nv_bfloat16 hh = __float2bfloat16(hn);
            ahb[r*ROWH + tH] = hh;
            alb[r*ROWH + tH] = __float2bfloat16(hn - __bfloat162float(hh));
            if (hob) hob[r*ROWH + tH] = hn;
        }
        __syncthreads();
    }
}

// ------------- attention -------------
__global__ __launch_bounds__(256,1)
void att_kernel(const float* __restrict__ u, const float* __restrict__ h1,
                const float* __restrict__ v, float* __restrict__ att)
{
    __shared__ float sa[Tt];
    __shared__ float red[256];
    __shared__ float vs[256];
    int b = blockIdx.x, tid = threadIdx.x;
    int wd = tid>>5, ln = tid&31;
    vs[tid] = v[tid];
    __syncthreads();
    for (int t = wd; t < Tt; t += 8){
        const float* ur = u + ((size_t)b*Tt + t)*256;
        float s = 0.f;
        #pragma unroll
        for (int j=0;j<8;j++) s += ur[ln+32*j]*vs[ln+32*j];
        #pragma unroll
        for (int o=16;o;o>>=1) s += __shfl_xor_sync(0xFFFFFFFFu, s, o);
        if (ln==0) sa[t] = s;
    }
    __syncthreads();
    float m = -3.4e38f;
    for (int t=tid;t<Tt;t+=256) m = fmaxf(m, sa[t]);
    red[tid] = m; __syncthreads();
    for (int off=128; off>0; off>>=1){ if (tid<off) red[tid]=fmaxf(red[tid],red[tid+off]); __syncthreads(); }
    float mx = red[0]; __syncthreads();
    float sum = 0.f;
    for (int t=tid;t<Tt;t+=256){ float e = __expf(sa[t]-mx); sa[t]=e; sum+=e; }
    red[tid] = sum; __syncthreads();
    for (int off=128; off>0; off>>=1){ if (tid<off) red[tid]+=red[tid+off]; __syncthreads(); }
    float inv = __fdividef(1.f, red[0]);
    __syncthreads();
    float acc = 0.f;
    const float* hb = h1 + (size_t)b*Tt*256 + tid;
    #pragma unroll 4
    for (int t=0;t<Tt;t++) acc += hb[(size_t)t*256] * sa[t];
    att[b*256 + tid] = acc * inv;
}

// ------------- launch -------------
extern "C" void kernel_launch(void* const* d_in, const int* in_sizes, int n_in,
                              void* d_out, int out_size)
{
    const float* X      = (const float*)d_in[0];
    const float* wih0f  = (const float*)d_in[1];
    const float* whh0f  = (const float*)d_in[2];
    const float* bih0f  = (const float*)d_in[3];
    const float* bhh0f  = (const float*)d_in[4];
    const float* wih0b  = (const float*)d_in[5];
    const float* whh0b  = (const float*)d_in[6];
    const float* bih0b  = (const float*)d_in[7];
    const float* bhh0b  = (const float*)d_in[8];
    const float* wih1f  = (const float*)d_in[9];
    const float* whh1f  = (const float*)d_in[10];
    const float* bih1f  = (const float*)d_in[11];
    const float* bhh1f  = (const float*)d_in[12];
    const float* wih1b  = (const float*)d_in[13];
    const float* whh1b  = (const float*)d_in[14];
    const float* bih1b  = (const float*)d_in[15];
    const float* bhh1b  = (const float*)d_in[16];
    const float* attW   = (const float*)d_in[17];
    const float* attV   = (const float*)d_in[18];
    const float* headW  = (const float*)d_in[19];
    const float* headB  = (const float*)d_in[20];
    float* out = (float*)d_out;

    cudaFuncSetAttribute(scan_kernel, cudaFuncAttributeMaxDynamicSharedMemorySize, SCAN_SMEM);
    cudaFuncSetAttribute(mma_gemm,    cudaFuncAttributeMaxDynamicSharedMemorySize, MMA_SMEM);

    float *xwF, *xwB, *h1, *wT, *bsum, *att;
    __nv_bfloat16 *ahi, *alo, *whi, *wlo;
    cudaGetSymbolAddress((void**)&xwF, g_xwF);
    cudaGetSymbolAddress((void**)&xwB, g_xwB);
    cudaGetSymbolAddress((void**)&h1,  g_h1);
    cudaGetSymbolAddress((void**)&wT,  g_wT);
    cudaGetSymbolAddress((void**)&bsum,g_bsum);
    cudaGetSymbolAddress((void**)&att, g_att);
    cudaGetSymbolAddress((void**)&ahi, g_ahi);
    cudaGetSymbolAddress((void**)&alo, g_alo);
    cudaGetSymbolAddress((void**)&whi, g_whi);
    cudaGetSymbolAddress((void**)&wlo, g_wlo);

    // launch order tuned so mma_gemm(0F) is the 6th launch (ncu -s 5 -c 1)
    // 1: x transpose + split
    transpose_split<<<dim3((Tt+31)/32,(KP0+31)/32,Bsz), dim3(32,8)>>>(X, ahi, alo);
    // 2,3: w_ih reorder+split (both layers, both directions)
    wsplit<<<(2*G4*KP0+255)/256,256>>>(wih0f, wih0b, whi+WOFF0F, wlo+WOFF0F, whi+WOFF0B, wlo+WOFF0B, Cc, KP0);
    wsplit<<<(2*G4*256+255)/256,256>>>(wih1f, wih1b, whi+WOFF1F, wlo+WOFF1F, whi+WOFF1B, wlo+WOFF1B, 256, 256);
    // 4: attention W split
    conv_splitT<<<(256*256+255)/256,256>>>(attW, whi+WOFFATT, wlo+WOFFATT, 256, 256, 256);
    // 5: W_hh reorders + bias folds
    whh_fold<<<(4*Hh*G4 + 4*G4 + 255)/256,256>>>(whh0f, whh0b, whh1f, whh1b,
        bih0f, bhh0f, bih0b, bhh0b, bih1f, bhh1f, bih1b, bhh1b, wT, bsum);

    // layer 0
    dim3 g0(4, BT/128);
    mma_gemm<<<g0,256,MMA_SMEM>>>(ahi, alo, whi+WOFF0F, wlo+WOFF0F, bsum + 0*G4, xwF, BT, G4, KP0, 0);  // 6th
    mma_gemm<<<g0,256,MMA_SMEM>>>(ahi, alo, whi+WOFF0B, wlo+WOFF0B, bsum + 1*G4, xwB, BT, G4, KP0, 0);
    scan_kernel<<<128,128,SCAN_SMEM>>>(xwF, xwB, wT + 0*Hh*G4, wT + 1*Hh*G4, ahi, alo, (float*)0);

    // layer 1 (A = h0 splits written by scan0, K=256)
    mma_gemm<<<g0,256,MMA_SMEM>>>(ahi, alo, whi+WOFF1F, wlo+WOFF1F, bsum + 2*G4, xwF, BT, G4, 256, 0);
    mma_gemm<<<g0,256,MMA_SMEM>>>(ahi, alo, whi+WOFF1B, wlo+WOFF1B, bsum + 3*G4, xwB, BT, G4, 256, 0);
    scan_kernel<<<128,128,SCAN_SMEM>>>(xwF, xwB, wT + 2*Hh*G4, wT + 3*Hh*G4, ahi, alo, h1);

    // attention u = tanh(h1 @ att_W)  (A = h1 splits from scan1)
    mma_gemm<<<dim3(2, BT/128),256,MMA_SMEM>>>(ahi, alo, whi+WOFFATT, wlo+WOFFATT, (const float*)0, xwF, BT, 256, 256, 1);
    att_kernel<<<Bsz,256>>>(xwF, h1, attV, att);
    // head (fp32)
    gemm128<<<dim3((NCLS+127)/128,(Bsz+127)/128),256>>>(att, headW, headB, out, Bsz, NCLS, 256, 1, 0);
}

// round 15
// speedup vs baseline: 1.7881x; 1.0212x over previous
#include <cuda_runtime.h>
#include <cuda_bf16.h>
#include <cstdint>

#define Bsz 512
#define Cc  271
#define Tt  281
#define Hh  128
#define NCLS 1854
#define BT  (Bsz*Tt)      /* 143872 */
#define G4  512
#define KP0 320           /* padded K for layer0 (multiple of 64) */

typedef unsigned long long u64;
typedef unsigned int u32;

union F4 { float4 v; float f[4]; u64 d[2]; };

__device__ __forceinline__ u64 ffma2(u64 a, u64 b, u64 c){
    u64 d; asm("fma.rn.f32x2 %0, %1, %2, %3;" : "=l"(d) : "l"(a), "l"(b), "l"(c)); return d;
}
__device__ __forceinline__ float2 unpack2(u64 d){
    float lo, hi; asm("mov.b64 {%0, %1}, %2;" : "=f"(lo), "=f"(hi) : "l"(d));
    return make_float2(lo, hi);
}
__device__ __forceinline__ float sigf(float x){ return __fdividef(1.f, 1.f + __expf(-x)); }
__device__ __forceinline__ float tanh_(float x){ return 1.f - __fdividef(2.f, __expf(2.f*x) + 1.f); }

// ------------- device scratch -------------
__device__ float g_xwF[(size_t)BT*G4];
__device__ float g_xwB[(size_t)BT*G4];
__device__ float g_h1 [(size_t)BT*2*Hh];
__device__ float g_wT [4*Hh*G4];          // 4x [128][512] gate-interleaved W_hh^T
__device__ float g_bsum[4*G4];
__device__ float g_att[Bsz*2*Hh];
// bf16 split buffers (A operand: x for layer0, h for layer1/att)
__device__ __nv_bfloat16 g_ahi[(size_t)BT*KP0];
__device__ __nv_bfloat16 g_alo[(size_t)BT*KP0];
#define WOFF0F 0
#define WOFF0B (512*KP0)
#define WOFF1F (2*512*KP0)
#define WOFF1B (2*512*KP0 + 512*256)
#define WOFFATT (2*512*KP0 + 2*512*256)
#define WTOT (WOFFATT + 256*256)
__device__ __nv_bfloat16 g_whi[WTOT];
__device__ __nv_bfloat16 g_wlo[WTOT];

__device__ __forceinline__ int oldrow(int n){ return (n&3)*128 + (n>>2); }

// ------------- fused prep kernels -------------
__global__ void wsplit(const float* __restrict__ srcF, const float* __restrict__ srcB,
                       __nv_bfloat16* __restrict__ hiF, __nv_bfloat16* __restrict__ loF,
                       __nv_bfloat16* __restrict__ hiB, __nv_bfloat16* __restrict__ loB,
                       int Ks, int Kp){
    int i = blockIdx.x*256 + threadIdx.x;
    if (i >= 2*G4*Kp) return;
    int half = i / (G4*Kp);
    int j = i - half*(G4*Kp);
    int n = j / Kp, k = j - n*Kp;
    const float* s = half ? srcB : srcF;
    float v = (k < Ks) ? s[oldrow(n)*Ks + k] : 0.f;
    __nv_bfloat16 h = __float2bfloat16(v);
    (half ? hiB : hiF)[j] = h;
    (half ? loB : loF)[j] = __float2bfloat16(v - __bfloat162float(h));
}
__global__ void conv_splitT(const float* __restrict__ src, __nv_bfloat16* __restrict__ hi,
                            __nv_bfloat16* __restrict__ lo, int N, int Ks, int Kp){
    int i = blockIdx.x*256 + threadIdx.x;
    if (i >= N*Kp) return;
    int n = i / Kp, k = i - n*Kp;
    float v = (k < Ks) ? src[(size_t)k*N + n] : 0.f;
    __nv_bfloat16 h = __float2bfloat16(v);
    hi[i] = h;
    lo[i] = __float2bfloat16(v - __bfloat162float(h));
}
__global__ void whh_fold(const float* __restrict__ w0, const float* __restrict__ w1,
                         const float* __restrict__ w2, const float* __restrict__ w3,
                         const float* __restrict__ bi0, const float* __restrict__ bh0,
                         const float* __restrict__ bi1, const float* __restrict__ bh1,
                         const float* __restrict__ bi2, const float* __restrict__ bh2,
                         const float* __restrict__ bi3, const float* __restrict__ bh3,
                         float* __restrict__ wT, float* __restrict__ bsum){
    int i = blockIdx.x*256 + threadIdx.x;
    if (i < 4*Hh*G4){
        int m = i / (Hh*G4);
        int r = i - m*(Hh*G4);
        int k = r >> 9, n = r & 511;
        const float* w = (m==0)?w0:(m==1)?w1:(m==2)?w2:w3;
        wT[i] = w[oldrow(n)*Hh + k];
    } else if (i < 4*Hh*G4 + 4*G4){
        int j = i - 4*Hh*G4;
        int m = j / G4, n = j - m*G4;
        const float* bi = (m==0)?bi0:(m==1)?bi1:(m==2)?bi2:bi3;
        const float* bh = (m==0)?bh0:(m==1)?bh1:(m==2)?bh2:bh3;
        int o = oldrow(n);
        bsum[j] = bi[o] + bh[o];
    }
}

// ------------- transpose X[B,C,T] -> split bf16 A[B*T, KP0] -------------
__global__ void transpose_split(const float* __restrict__ X,
                                __nv_bfloat16* __restrict__ hi,
                                __nv_bfloat16* __restrict__ lo){
    __shared__ float tile[32][33];
    int b = blockIdx.z;
    int t0 = blockIdx.x*32, c0 = blockIdx.y*32;
    int tx = threadIdx.x, ty = threadIdx.y;
    const float* Xb = X + (size_t)b*Cc*Tt;
    #pragma unroll
    for (int i=0;i<32;i+=8){
        int c = c0+ty+i, t = t0+tx;
        tile[ty+i][tx] = (c<Cc && t<Tt) ? Xb[(size_t)c*Tt + t] : 0.f;
    }
    __syncthreads();
    #pragma unroll
    for (int i=0;i<32;i+=8){
        int t = t0+ty+i, c = c0+tx;
        if (t<Tt){
            float v = tile[tx][ty+i];
            __nv_bfloat16 h = __float2bfloat16(v);
            size_t idx = ((size_t)b*Tt + t)*KP0 + c;
            hi[idx] = h;
            lo[idx] = __float2bfloat16(v - __bfloat162float(h));
        }
    }
}

// ------- tensor-core GEMM, split-bf16 (3 passes), 128x256 CTA tile, K64 chunks --
#define SST2 72                   /* smem row stride in halves (64 data + 8 pad) */
#define TSZA (128*SST2)
#define TSZW (256*SST2)
#define STGH (2*TSZA + 2*TSZW)    /* stage size in halves */
#define MMA_SMEM (2*STGH*2)       /* bytes = 221184 */
__device__ __forceinline__ u32 smaddr(const void* p){ return (u32)__cvta_generic_to_shared(p); }
__device__ __forceinline__ void cpasync16(u32 s, const void* g){
    asm volatile("cp.async.cg.shared.global [%0], [%1], 16;" :: "r"(s), "l"(g));
}
__device__ __forceinline__ void ldsm4(u32* r, u32 a){
    asm volatile("ldmatrix.sync.aligned.m8n8.x4.shared.b16 {%0,%1,%2,%3}, [%4];"
        : "=r"(r[0]),"=r"(r[1]),"=r"(r[2]),"=r"(r[3]) : "r"(a));
}
__device__ __forceinline__ void mma16816(float* d, const u32* a, u32 b0, u32 b1){
    asm volatile("mma.sync.aligned.m16n8k16.row.col.f32.bf16.bf16.f32 "
        "{%0,%1,%2,%3}, {%4,%5,%6,%7}, {%8,%9}, {%0,%1,%2,%3};"
        : "+f"(d[0]),"+f"(d[1]),"+f"(d[2]),"+f"(d[3])
        : "r"(a[0]),"r"(a[1]),"r"(a[2]),"r"(a[3]), "r"(b0),"r"(b1));
}

__global__ __launch_bounds__(256,1)
void mma_gemm(const __nv_bfloat16* __restrict__ Ahi, const __nv_bfloat16* __restrict__ Alo,
              const __nv_bfloat16* __restrict__ Whi, const __nv_bfloat16* __restrict__ Wlo,
              const float* __restrict__ bias, float* __restrict__ C,
              int M, int N, int Kp, int act)
{
    extern __shared__ __align__(16) __nv_bfloat16 sm[];   // [2][STGH]
    int tid = threadIdx.x;
    int wid = tid>>5, lane = tid&31;
    int m0 = blockIdx.y*128, n0 = blockIdx.x*256;
    int wm = (wid>>2)*64, wn = (wid&3)*64;

    float acc[4][8][4];
    #pragma unroll
    for (int i=0;i<4;i++)
      #pragma unroll
      for (int j=0;j<8;j++)
        #pragma unroll
        for (int q=0;q<4;q++) acc[i][j][q] = 0.f;

    const __nv_bfloat16* gA[2];
    const __nv_bfloat16* gW[2];
    gA[0] = Ahi + (size_t)m0*Kp;
    gA[1] = Alo + (size_t)m0*Kp;
    gW[0] = Whi + (size_t)n0*Kp;
    gW[1] = Wlo + (size_t)n0*Kp;

    int NC = Kp >> 6;                       // 64-wide chunks
    int lrow = tid>>3, lseg = tid&7;

    {   // prologue: chunk 0 -> stage 0
        #pragma unroll
        for (int v=0;v<2;v++){
            #pragma unroll
            for (int i=0;i<4;i++){
                int row = lrow + i*32;
                cpasync16(smaddr(&sm[v*TSZA + row*SST2 + lseg*8]),
                          gA[v] + (size_t)row*Kp + lseg*8);
            }
            #pragma unroll
            for (int i=0;i<8;i++){
                int row = lrow + i*32;
                cpasync16(smaddr(&sm[2*TSZA + v*TSZW + row*SST2 + lseg*8]),
                          gW[v] + (size_t)row*Kp + lseg*8);
            }
        }
        asm volatile("cp.async.commit_group;" ::: "memory");
    }

    int ar = lane & 15;
    int ac = (lane >> 4) * 8;
    int brn = (lane & 7) + ((lane & 16) ? 8 : 0);
    int bc  = (lane & 8) ? 8 : 0;

    for (int c=0;c<NC;c++){
        if (c+1 < NC){
            int k0 = (c+1)*64, s = (c+1)&1;
            #pragma unroll
            for (int v=0;v<2;v++){
                #pragma unroll
                for (int i=0;i<4;i++){
                    int row = lrow + i*32;
                    cpasync16(smaddr(&sm[s*STGH + v*TSZA + row*SST2 + lseg*8]),
                              gA[v] + (size_t)row*Kp + k0 + lseg*8);
                }
                #pragma unroll
                for (int i=0;i<8;i++){
                    int row = lrow + i*32;
                    cpasync16(smaddr(&sm[s*STGH + 2*TSZA + v*TSZW + row*SST2 + lseg*8]),
                              gW[v] + (size_t)row*Kp + k0 + lseg*8);
                }
            }
            asm volatile("cp.async.commit_group;" ::: "memory");
            asm volatile("cp.async.wait_group 1;" ::: "memory");
        } else {
            asm volatile("cp.async.wait_group 0;" ::: "memory");
        }
        __syncthreads();
        int s = c & 1;
        const __nv_bfloat16* tA_hi = sm + s*STGH;
        const __nv_bfloat16* tA_lo = sm + s*STGH + TSZA;
        const __nv_bfloat16* tW_hi = sm + s*STGH + 2*TSZA;
        const __nv_bfloat16* tW_lo = sm + s*STGH + 2*TSZA + TSZW;

        #pragma unroll
        for (int ks=0; ks<4; ks++){
            int ko = ks*16;
            u32 Af[4][4], Whf[4][4], Wlf[4][4];
            #pragma unroll
            for (int mi=0;mi<4;mi++)
                ldsm4(Af[mi], smaddr(&tA_hi[(wm + mi*16 + ar)*SST2 + ko + ac]));
            #pragma unroll
            for (int g=0;g<4;g++)
                ldsm4(Whf[g], smaddr(&tW_hi[(wn + g*16 + brn)*SST2 + ko + bc]));
            // pass 1: Ahi * Whi
            #pragma unroll
            for (int mi=0;mi<4;mi++)
                #pragma unroll
                for (int ni=0;ni<8;ni++)
                    mma16816(acc[mi][ni], Af[mi], Whf[ni>>1][(ni&1)*2], Whf[ni>>1][(ni&1)*2+1]);
            // pass 2: Ahi * Wlo
            #pragma unroll
            for (int g=0;g<4;g++)
                ldsm4(Wlf[g], smaddr(&tW_lo[(wn + g*16 + brn)*SST2 + ko + bc]));
            #pragma unroll
            for (int mi=0;mi<4;mi++)
                #pragma unroll
                for (int ni=0;ni<8;ni++)
                    mma16816(acc[mi][ni], Af[mi], Wlf[ni>>1][(ni&1)*2], Wlf[ni>>1][(ni&1)*2+1]);
            // pass 3: Alo * Whi
            #pragma unroll
            for (int mi=0;mi<4;mi++)
                ldsm4(Af[mi], smaddr(&tA_lo[(wm + mi*16 + ar)*SST2 + ko + ac]));
            #pragma unroll
            for (int mi=0;mi<4;mi++)
                #pragma unroll
                for (int ni=0;ni<8;ni++)
                    mma16816(acc[mi][ni], Af[mi], Whf[ni>>1][(ni&1)*2], Whf[ni>>1][(ni&1)*2+1]);
        }
        __syncthreads();
    }

    // epilogue
    int er = lane>>2, ec = (lane&3)*2;
    #pragma unroll
    for (int mi=0;mi<4;mi++){
        #pragma unroll
        for (int ni=0;ni<8;ni++){
            int gm = m0 + wm + mi*16 + er;
            int gn = n0 + wn + ni*8 + ec;
            float b0 = bias ? bias[gn]   : 0.f;
            float b1 = bias ? bias[gn+1] : 0.f;
            float v0 = acc[mi][ni][0] + b0;
            float v1 = acc[mi][ni][1] + b1;
            float v2 = acc[mi][ni][2] + b0;
            float v3 = acc[mi][ni][3] + b1;
            if (act){ v0 = tanh_(v0); v1 = tanh_(v1); v2 = tanh_(v2); v3 = tanh_(v3); }
            *(float2*)&C[(size_t)gm*N + gn]     = make_float2(v0, v1);
            *(float2*)&C[(size_t)(gm+8)*N + gn] = make_float2(v2, v3);
        }
    }
}

// ------------- fp32 GEMM (head only) -------------
__global__ __launch_bounds__(256,2)
void gemm128(const float* __restrict__ A, const float* __restrict__ B,
             const float* __restrict__ bias, float* __restrict__ C,
             int M, int N, int K, int transB, int act)
{
    __shared__ float As2[16][264];
    __shared__ float Bs[16][132];
    int row0 = blockIdx.y*128, col0 = blockIdx.x*128;
    int tid = threadIdx.x;
    int tm = tid >> 4, tn = tid & 15;
    u64 acc[8][4];
    #pragma unroll
    for (int i=0;i<8;i++)
        #pragma unroll
        for (int j=0;j<4;j++) acc[i][j] = 0ull;

    for (int k0=0;k0<K;k0+=16){
        #pragma unroll
        for (int i=0;i<8;i++){
            int idx = tid + i*256;
            int r = idx >> 4, kk = idx & 15;
            int gr = row0+r, gk = k0+kk;
            float v = (gr<M && gk<K) ? A[(size_t)gr*K + gk] : 0.f;
            *(float2*)&As2[kk][2*r] = make_float2(v, v);
        }
        if (transB){
            #pragma unroll
            for (int i=0;i<8;i++){
                int idx = tid + i*256;
                int nn = idx >> 4, kk = idx & 15;
                int gk = k0+kk, gn = col0+nn;
                Bs[kk][nn] = (gk<K && gn<N) ? B[(size_t)gn*K+gk] : 0.f;
            }
        } else {
            #pragma unroll
            for (int i=0;i<8;i++){
                int idx = tid + i*256;
                int nn = idx & 127, kk = idx >> 7;
                int gk = k0+kk, gn = col0+nn;
                Bs[kk][nn] = (gk<K && gn<N) ? B[(size_t)gk*N+gn] : 0.f;
            }
        }
        __syncthreads();
        #pragma unroll
        for (int kk=0;kk<16;kk++){
            F4 b0, b1, a0, a1, a2, a3;
            b0.v = *(const float4*)&Bs[kk][tn*8];
            b1.v = *(const float4*)&Bs[kk][tn*8+4];
            a0.v = *(const float4*)&As2[kk][tm*16];
            a1.v = *(const float4*)&As2[kk][tm*16+4];
            a2.v = *(const float4*)&As2[kk][tm*16+8];
            a3.v = *(const float4*)&As2[kk][tm*16+12];
            u64 bd[4] = { b0.d[0], b0.d[1], b1.d[0], b1.d[1] };
            u64 ad[8] = { a0.d[0], a0.d[1], a1.d[0], a1.d[1],
                          a2.d[0], a2.d[1], a3.d[0], a3.d[1] };
            #pragma unroll
            for (int i=0;i<8;i++)
                #pragma unroll
                for (int j=0;j<4;j++)
                    acc[i][j] = ffma2(ad[i], bd[j], acc[i][j]);
        }
        __syncthreads();
    }
    #pragma unroll
    for (int i=0;i<8;i++){
        int gr = row0 + tm*8 + i;
        if (gr >= M) continue;
        #pragma unroll
        for (int j=0;j<4;j++){
            float2 v = unpack2(acc[i][j]);
            int gn = col0 + tn*8 + j*2;
            if (gn < N){
                float x = v.x + (bias ? bias[gn] : 0.f);
                if (act) x = tanh_(x);
                C[(size_t)gr*N + gn] = x;
            }
            if (gn+1 < N){
                float y = v.y + (bias ? bias[gn+1] : 0.f);
                if (act) y = tanh_(y);
                C[(size_t)gr*N + gn+1] = y;
            }
        }
    }
}

// ------------- LSTM scan: 128 threads, 8 rows/thread (W read once per step) ----
#define HS 20
#define SCAN_SMEM ((64*G4 + 2*128*HS)*4)
#define ROWX ((size_t)Tt*G4)
#define ROWH ((size_t)Tt*256)

__global__ __launch_bounds__(128,1)
void scan_kernel(const float* __restrict__ xwFp, const float* __restrict__ xwBp,
                 const float* __restrict__ wTF, const float* __restrict__ wTB,
                 __nv_bfloat16* __restrict__ ahi, __nv_bfloat16* __restrict__ alo,
                 float* __restrict__ hout)
{
    extern __shared__ float smf[];
    float* Ws  = smf;                 // 64 x 512
    float* hsA = smf + 64*G4;         // 128 x HS (dup pairs of 8 rows)
    float* hsB = hsA + 128*HS;
    int h = threadIdx.x;              // 0..127
    int dir = blockIdx.x >> 6;
    int grp = blockIdx.x & 63;
    int b0 = grp*8;
    const float* xw = dir ? xwBp : xwFp;
    const float* wD = dir ? wTB : wTF;
    int hOff = dir*128;

    for (int i=h;i<64*G4;i+=128) Ws[i] = wD[i];
    for (int i=h;i<2*128*HS;i+=128) hsA[i] = 0.f;
    float cst[8] = {0.f,0.f,0.f,0.f,0.f,0.f,0.f,0.f};

    const float* xb = xw + (size_t)b0*ROWX + 4*h;
    __nv_bfloat16* ahb = ahi + (size_t)b0*ROWH + hOff + h;
    __nv_bfloat16* alb = alo + (size_t)b0*ROWH + hOff + h;
    float* hob = hout ? (hout + (size_t)b0*ROWH + hOff + h) : (float*)0;
    __syncthreads();

    for (int s=0;s<Tt;s++){
        int t = dir ? (Tt-1-s) : s;
        float* hsR = (s&1) ? hsB : hsA;
        float* hsW = (s&1) ? hsA : hsB;

        F4 xv[8];
        size_t tX = (size_t)t*G4;
        #pragma unroll
        for (int r=0;r<8;r++) xv[r].v = *(const float4*)&xb[r*ROWX + tX];

        u64 aIF[8] = {0,0,0,0,0,0,0,0}, aGO[8] = {0,0,0,0,0,0,0,0};
        #pragma unroll 4
        for (int k=0;k<64;k++){
            F4 w;  w.v  = *(const float4*)&Ws[k*G4 + 4*h];
            F4 p0; p0.v = *(const float4*)&hsR[k*HS];
            F4 p1; p1.v = *(const float4*)&hsR[k*HS + 4];
            F4 p2; p2.v = *(const float4*)&hsR[k*HS + 8];
            F4 p3; p3.v = *(const float4*)&hsR[k*HS + 12];
            aIF[0]=ffma2(p0.d[0], w.d[0], aIF[0]); aGO[0]=ffma2(p0.d[0], w.d[1], aGO[0]);
            aIF[1]=ffma2(p0.d[1], w.d[0], aIF[1]); aGO[1]=ffma2(p0.d[1], w.d[1], aGO[1]);
            aIF[2]=ffma2(p1.d[0], w.d[0], aIF[2]); aGO[2]=ffma2(p1.d[0], w.d[1], aGO[2]);
            aIF[3]=ffma2(p1.d[1], w.d[0], aIF[3]); aGO[3]=ffma2(p1.d[1], w.d[1], aGO[3]);
            aIF[4]=ffma2(p2.d[0], w.d[0], aIF[4]); aGO[4]=ffma2(p2.d[0], w.d[1], aGO[4]);
            aIF[5]=ffma2(p2.d[1], w.d[0], aIF[5]); aGO[5]=ffma2(p2.d[1], w.d[1], aGO[5]);
            aIF[6]=ffma2(p3.d[0], w.d[0], aIF[6]); aGO[6]=ffma2(p3.d[0], w.d[1], aGO[6]);
            aIF[7]=ffma2(p3.d[1], w.d[0], aIF[7]); aGO[7]=ffma2(p3.d[1], w.d[1], aGO[7]);
        }
        for (int kb=64;kb<128;kb+=8){
            F4 w[8];
            #pragma unroll
            for (int j=0;j<8;j++) w[j].v = *(const float4*)&wD[(size_t)(kb+j)*G4 + 4*h];
            #pragma unroll
            for (int j=0;j<8;j++){
                int k = kb+j;
                F4 p0; p0.v = *(const float4*)&hsR[k*HS];
                F4 p1; p1.v = *(const float4*)&hsR[k*HS + 4];
                F4 p2; p2.v = *(const float4*)&hsR[k*HS + 8];
                F4 p3; p3.v = *(const float4*)&hsR[k*HS + 12];
                aIF[0]=ffma2(p0.d[0], w[j].d[0], aIF[0]); aGO[0]=ffma2(p0.d[0], w[j].d[1], aGO[0]);
                aIF[1]=ffma2(p0.d[1], w[j].d[0], aIF[1]); aGO[1]=ffma2(p0.d[1], w[j].d[1], aGO[1]);
                aIF[2]=ffma2(p1.d[0], w[j].d[0], aIF[2]); aGO[2]=ffma2(p1.d[0], w[j].d[1], aGO[2]);
                aIF[3]=ffma2(p1.d[1], w[j].d[0], aIF[3]); aGO[3]=ffma2(p1.d[1], w[j].d[1], aGO[3]);
                aIF[4]=ffma2(p2.d[0], w[j].d[0], aIF[4]); aGO[4]=ffma2(p2.d[0], w[j].d[1], aGO[4]);
                aIF[5]=ffma2(p2.d[1], w[j].d[0], aIF[5]); aGO[5]=ffma2(p2.d[1], w[j].d[1], aGO[5]);
                aIF[6]=ffma2(p3.d[0], w[j].d[0], aIF[6]); aGO[6]=ffma2(p3.d[0], w[j].d[1], aGO[6]);
                aIF[7]=ffma2(p3.d[1], w[j].d[0], aIF[7]); aGO[7]=ffma2(p3.d[1], w[j].d[1], aGO[7]);
            }
        }
        size_t tH = (size_t)t*256;
        #pragma unroll
        for (int r=0;r<8;r++){
            float2 v1 = unpack2(aIF[r]);
            float2 v2 = unpack2(aGO[r]);
            float gi = v1.x + xv[r].f[0];
            float gf = v1.y + xv[r].f[1];
            float gg = v2.x + xv[r].f[2];
            float go = v2.y + xv[r].f[3];
            float cc = sigf(gf)*cst[r] + sigf(gi)*tanh_(gg);
            cst[r] = cc;
            float hn = sigf(go)*tanh_(cc);
            *(float2*)&hsW[h*HS + 2*r] = make_float2(hn, hn);
            __nv_bfloat16 hh = __float2bfloat16(hn);
            ahb[r*ROWH + tH] = hh;
            alb[r*ROWH + tH] = __float2bfloat16(hn - __bfloat162float(hh));
            if (hob) hob[r*ROWH + tH] = hn;
        }
        __syncthreads();
    }
}

// ------------- attention -------------
__global__ __launch_bounds__(256,1)
void att_kernel(const float* __restrict__ u, const float* __restrict__ h1,
                const float* __restrict__ v, float* __restrict__ att)
{
    __shared__ float sa[Tt];
    __shared__ float red[256];
    __shared__ float vs[256];
    int b = blockIdx.x, tid = threadIdx.x;
    int wd = tid>>5, ln = tid&31;
    vs[tid] = v[tid];
    __syncthreads();
    for (int t = wd; t < Tt; t += 8){
        const float* ur = u + ((size_t)b*Tt + t)*256;
        float s = 0.f;
        #pragma unroll
        for (int j=0;j<8;j++) s += ur[ln+32*j]*vs[ln+32*j];
        #pragma unroll
        for (int o=16;o;o>>=1) s += __shfl_xor_sync(0xFFFFFFFFu, s, o);
        if (ln==0) sa[t] = s;
    }
    __syncthreads();
    float m = -3.4e38f;
    for (int t=tid;t<Tt;t+=256) m = fmaxf(m, sa[t]);
    red[tid] = m; __syncthreads();
    for (int off=128; off>0; off>>=1){ if (tid<off) red[tid]=fmaxf(red[tid],red[tid+off]); __syncthreads(); }
    float mx = red[0]; __syncthreads();
    float sum = 0.f;
    for (int t=tid;t<Tt;t+=256){ float e = __expf(sa[t]-mx); sa[t]=e; sum+=e; }
    red[tid] = sum; __syncthreads();
    for (int off=128; off>0; off>>=1){ if (tid<off) red[tid]+=red[tid+off]; __syncthreads(); }
    float inv = __fdividef(1.f, red[0]);
    __syncthreads();
    float acc = 0.f;
    const float* hb = h1 + (size_t)b*Tt*256 + tid;
    #pragma unroll 4
    for (int t=0;t<Tt;t++) acc += hb[(size_t)t*256] * sa[t];
    att[b*256 + tid] = acc * inv;
}

// ------------- launch -------------
extern "C" void kernel_launch(void* const* d_in, const int* in_sizes, int n_in,
                              void* d_out, int out_size)
{
    const float* X      = (const float*)d_in[0];
    const float* wih0f  = (const float*)d_in[1];
    const float* whh0f  = (const float*)d_in[2];
    const float* bih0f  = (const float*)d_in[3];
    const float* bhh0f  = (const float*)d_in[4];
    const float* wih0b  = (const float*)d_in[5];
    const float* whh0b  = (const float*)d_in[6];
    const float* bih0b  = (const float*)d_in[7];
    const float* bhh0b  = (const float*)d_in[8];
    const float* wih1f  = (const float*)d_in[9];
    const float* whh1f  = (const float*)d_in[10];
    const float* bih1f  = (const float*)d_in[11];
    const float* bhh1f  = (const float*)d_in[12];
    const float* wih1b  = (const float*)d_in[13];
    const float* whh1b  = (const float*)d_in[14];
    const float* bih1b  = (const float*)d_in[15];
    const float* bhh1b  = (const float*)d_in[16];
    const float* attW   = (const float*)d_in[17];
    const float* attV   = (const float*)d_in[18];
    const float* headW  = (const float*)d_in[19];
    const float* headB  = (const float*)d_in[20];
    float* out = (float*)d_out;

    cudaFuncSetAttribute(scan_kernel, cudaFuncAttributeMaxDynamicSharedMemorySize, SCAN_SMEM);
    cudaFuncSetAttribute(mma_gemm,    cudaFuncAttributeMaxDynamicSharedMemorySize, MMA_SMEM);

    float *xwF, *xwB, *h1, *wT, *bsum, *att;
    __nv_bfloat16 *ahi, *alo, *whi, *wlo;
    cudaGetSymbolAddress((void**)&xwF, g_xwF);
    cudaGetSymbolAddress((void**)&xwB, g_xwB);
    cudaGetSymbolAddress((void**)&h1,  g_h1);
    cudaGetSymbolAddress((void**)&wT,  g_wT);
    cudaGetSymbolAddress((void**)&bsum,g_bsum);
    cudaGetSymbolAddress((void**)&att, g_att);
    cudaGetSymbolAddress((void**)&ahi, g_ahi);
    cudaGetSymbolAddress((void**)&alo, g_alo);
    cudaGetSymbolAddress((void**)&whi, g_whi);
    cudaGetSymbolAddress((void**)&wlo, g_wlo);

    // launch order: mma_gemm(0F) must be our 4th launch (ncu profiles our #4)
    transpose_split<<<dim3((Tt+31)/32,(KP0+31)/32,Bsz), dim3(32,8)>>>(X, ahi, alo);       // 1
    wsplit<<<(2*G4*KP0+255)/256,256>>>(wih0f, wih0b, whi+WOFF0F, wlo+WOFF0F,
                                       whi+WOFF0B, wlo+WOFF0B, Cc, KP0);                   // 2
    whh_fold<<<(4*Hh*G4 + 4*G4 + 255)/256,256>>>(whh0f, whh0b, whh1f, whh1b,
        bih0f, bhh0f, bih0b, bhh0b, bih1f, bhh1f, bih1b, bhh1b, wT, bsum);                 // 3

    dim3 g0(2, BT/128);
    mma_gemm<<<g0,256,MMA_SMEM>>>(ahi, alo, whi+WOFF0F, wlo+WOFF0F, bsum + 0*G4, xwF, BT, G4, KP0, 0); // 4 (profiled)
    mma_gemm<<<g0,256,MMA_SMEM>>>(ahi, alo, whi+WOFF0B, wlo+WOFF0B, bsum + 1*G4, xwB, BT, G4, KP0, 0);
    // independent prep for later stages (fills the gap before scan0 retires)
    wsplit<<<(2*G4*256+255)/256,256>>>(wih1f, wih1b, whi+WOFF1F, wlo+WOFF1F,
                                       whi+WOFF1B, wlo+WOFF1B, 256, 256);
    conv_splitT<<<(256*256+255)/256,256>>>(attW, whi+WOFFATT, wlo+WOFFATT, 256, 256, 256);
    scan_kernel<<<128,128,SCAN_SMEM>>>(xwF, xwB, wT + 0*Hh*G4, wT + 1*Hh*G4, ahi, alo, (float*)0);

    // layer 1 (A = h0 splits written by scan0, K=256)
    mma_gemm<<<g0,256,MMA_SMEM>>>(ahi, alo, whi+WOFF1F, wlo+WOFF1F, bsum + 2*G4, xwF, BT, G4, 256, 0);
    mma_gemm<<<g0,256,MMA_SMEM>>>(ahi, alo, whi+WOFF1B, wlo+WOFF1B, bsum + 3*G4, xwB, BT, G4, 256, 0);
    scan_kernel<<<128,128,SCAN_SMEM>>>(xwF, xwB, wT + 2*Hh*G4, wT + 3*Hh*G4, ahi, alo, h1);

    // attention u = tanh(h1 @ att_W)  (A = h1 splits from scan1)
    mma_gemm<<<dim3(1, BT/128),256,MMA_SMEM>>>(ahi, alo, whi+WOFFATT, wlo+WOFFATT, (const float*)0, xwF, BT, 256, 256, 1);
    att_kernel<<<Bsz,256>>>(xwF, h1, attV, att);
    // head (fp32)
    gemm128<<<dim3((NCLS+127)/128,(Bsz+127)/128),256>>>(att, headW, headB, out, Bsz, NCLS, 256, 1, 0);
}

// round 17
// speedup vs baseline: 1.9836x; 1.1093x over previous
#include <cuda_runtime.h>
#include <cuda_bf16.h>
#include <cstdint>

#define Bsz 512
#define Cc  271
#define Tt  281
#define Hh  128
#define NCLS 1854
#define BT  (Bsz*Tt)      /* 143872 */
#define G4  512
#define KP0 320           /* padded K for layer0 (multiple of 64) */

typedef unsigned long long u64;
typedef unsigned int u32;

union F4 { float4 v; float f[4]; u64 d[2]; };

__device__ __forceinline__ u64 ffma2(u64 a, u64 b, u64 c){
    u64 d; asm("fma.rn.f32x2 %0, %1, %2, %3;" : "=l"(d) : "l"(a), "l"(b), "l"(c)); return d;
}
__device__ __forceinline__ float2 unpack2(u64 d){
    float lo, hi; asm("mov.b64 {%0, %1}, %2;" : "=f"(lo), "=f"(hi) : "l"(d));
    return make_float2(lo, hi);
}
__device__ __forceinline__ float sigf(float x){ return __fdividef(1.f, 1.f + __expf(-x)); }
__device__ __forceinline__ float tanh_(float x){ return 1.f - __fdividef(2.f, __expf(2.f*x) + 1.f); }

// ------------- device scratch -------------
__device__ float g_xwF[(size_t)BT*G4];
__device__ float g_xwB[(size_t)BT*G4];
__device__ float g_h1 [(size_t)BT*2*Hh];
__device__ float g_wT [4*Hh*G4];          // 4x [128][512] gate-interleaved W_hh^T
__device__ float g_bsum[4*G4];
__device__ float g_att[Bsz*2*Hh];
// bf16 split buffers (A operand: x for layer0, h for layer1/att)
__device__ __nv_bfloat16 g_ahi[(size_t)BT*KP0];
__device__ __nv_bfloat16 g_alo[(size_t)BT*KP0];
#define WOFF0F 0
#define WOFF0B (512*KP0)
#define WOFF1F (2*512*KP0)
#define WOFF1B (2*512*KP0 + 512*256)
#define WOFFATT (2*512*KP0 + 2*512*256)
#define WTOT (WOFFATT + 256*256)
__device__ __nv_bfloat16 g_whi[WTOT];
__device__ __nv_bfloat16 g_wlo[WTOT];

__device__ __forceinline__ int oldrow(int n){ return (n&3)*128 + (n>>2); }

// ------------- fused prep kernels -------------
__global__ void wsplit(const float* __restrict__ srcF, const float* __restrict__ srcB,
                       __nv_bfloat16* __restrict__ hiF, __nv_bfloat16* __restrict__ loF,
                       __nv_bfloat16* __restrict__ hiB, __nv_bfloat16* __restrict__ loB,
                       int Ks, int Kp){
    int i = blockIdx.x*256 + threadIdx.x;
    if (i >= 2*G4*Kp) return;
    int half = i / (G4*Kp);
    int j = i - half*(G4*Kp);
    int n = j / Kp, k = j - n*Kp;
    const float* s = half ? srcB : srcF;
    float v = (k < Ks) ? s[oldrow(n)*Ks + k] : 0.f;
    __nv_bfloat16 h = __float2bfloat16(v);
    (half ? hiB : hiF)[j] = h;
    (half ? loB : loF)[j] = __float2bfloat16(v - __bfloat162float(h));
}
__global__ void conv_splitT(const float* __restrict__ src, __nv_bfloat16* __restrict__ hi,
                            __nv_bfloat16* __restrict__ lo, int N, int Ks, int Kp){
    int i = blockIdx.x*256 + threadIdx.x;
    if (i >= N*Kp) return;
    int n = i / Kp, k = i - n*Kp;
    float v = (k < Ks) ? src[(size_t)k*N + n] : 0.f;
    __nv_bfloat16 h = __float2bfloat16(v);
    hi[i] = h;
    lo[i] = __float2bfloat16(v - __bfloat162float(h));
}
__global__ void whh_fold(const float* __restrict__ w0, const float* __restrict__ w1,
                         const float* __restrict__ w2, const float* __restrict__ w3,
                         const float* __restrict__ bi0, const float* __restrict__ bh0,
                         const float* __restrict__ bi1, const float* __restrict__ bh1,
                         const float* __restrict__ bi2, const float* __restrict__ bh2,
                         const float* __restrict__ bi3, const float* __restrict__ bh3,
                         float* __restrict__ wT, float* __restrict__ bsum){
    int i = blockIdx.x*256 + threadIdx.x;
    if (i < 4*Hh*G4){
        int m = i / (Hh*G4);
        int r = i - m*(Hh*G4);
        int k = r >> 9, n = r & 511;
        const float* w = (m==0)?w0:(m==1)?w1:(m==2)?w2:w3;
        wT[i] = w[oldrow(n)*Hh + k];
    } else if (i < 4*Hh*G4 + 4*G4){
        int j = i - 4*Hh*G4;
        int m = j / G4, n = j - m*G4;
        const float* bi = (m==0)?bi0:(m==1)?bi1:(m==2)?bi2:bi3;
        const float* bh = (m==0)?bh0:(m==1)?bh1:(m==2)?bh2:bh3;
        int o = oldrow(n);
        bsum[j] = bi[o] + bh[o];
    }
}

// ------------- transpose X[B,C,T] -> split bf16 A[B*T, KP0] -------------
__global__ void transpose_split(const float* __restrict__ X,
                                __nv_bfloat16* __restrict__ hi,
                                __nv_bfloat16* __restrict__ lo){
    __shared__ float tile[32][33];
    int b = blockIdx.z;
    int t0 = blockIdx.x*32, c0 = blockIdx.y*32;
    int tx = threadIdx.x, ty = threadIdx.y;
    const float* Xb = X + (size_t)b*Cc*Tt;
    #pragma unroll
    for (int i=0;i<32;i+=8){
        int c = c0+ty+i, t = t0+tx;
        tile[ty+i][tx] = (c<Cc && t<Tt) ? Xb[(size_t)c*Tt + t] : 0.f;
    }
    __syncthreads();
    #pragma unroll
    for (int i=0;i<32;i+=8){
        int t = t0+ty+i, c = c0+tx;
        if (t<Tt){
            float v = tile[tx][ty+i];
            __nv_bfloat16 h = __float2bfloat16(v);
            size_t idx = ((size_t)b*Tt + t)*KP0 + c;
            hi[idx] = h;
            lo[idx] = __float2bfloat16(v - __bfloat162float(h));
        }
    }
}

// ------- tensor-core GEMM, split-bf16 (3 passes), 128x256 CTA tile, K64 chunks --
#define SST2 72                   /* smem row stride in halves (64 data + 8 pad) */
#define TSZA (128*SST2)
#define TSZW (256*SST2)
#define STGH (2*TSZA + 2*TSZW)    /* stage size in halves */
#define MMA_SMEM (2*STGH*2)       /* bytes = 221184 */
__device__ __forceinline__ u32 smaddr(const void* p){ return (u32)__cvta_generic_to_shared(p); }
__device__ __forceinline__ void cpasync16(u32 s, const void* g){
    asm volatile("cp.async.cg.shared.global [%0], [%1], 16;" :: "r"(s), "l"(g));
}
__device__ __forceinline__ void ldsm4(u32* r, u32 a){
    asm volatile("ldmatrix.sync.aligned.m8n8.x4.shared.b16 {%0,%1,%2,%3}, [%4];"
        : "=r"(r[0]),"=r"(r[1]),"=r"(r[2]),"=r"(r[3]) : "r"(a));
}
__device__ __forceinline__ void mma16816(float* d, const u32* a, u32 b0, u32 b1){
    asm volatile("mma.sync.aligned.m16n8k16.row.col.f32.bf16.bf16.f32 "
        "{%0,%1,%2,%3}, {%4,%5,%6,%7}, {%8,%9}, {%0,%1,%2,%3};"
        : "+f"(d[0]),"+f"(d[1]),"+f"(d[2]),"+f"(d[3])
        : "r"(a[0]),"r"(a[1]),"r"(a[2]),"r"(a[3]), "r"(b0),"r"(b1));
}

__global__ __launch_bounds__(256,1)
void mma_gemm(const __nv_bfloat16* __restrict__ Ahi, const __nv_bfloat16* __restrict__ Alo,
              const __nv_bfloat16* __restrict__ Whi, const __nv_bfloat16* __restrict__ Wlo,
              const float* __restrict__ bias, float* __restrict__ C,
              int M, int N, int Kp, int act)
{
    extern __shared__ __align__(16) __nv_bfloat16 sm[];   // [2][STGH]
    int tid = threadIdx.x;
    int wid = tid>>5, lane = tid&31;
    int m0 = blockIdx.y*128, n0 = blockIdx.x*256;
    int wm = (wid>>2)*64, wn = (wid&3)*64;

    float acc[4][8][4];
    #pragma unroll
    for (int i=0;i<4;i++)
      #pragma unroll
      for (int j=0;j<8;j++)
        #pragma unroll
        for (int q=0;q<4;q++) acc[i][j][q] = 0.f;

    const __nv_bfloat16* gA[2];
    const __nv_bfloat16* gW[2];
    gA[0] = Ahi + (size_t)m0*Kp;
    gA[1] = Alo + (size_t)m0*Kp;
    gW[0] = Whi + (size_t)n0*Kp;
    gW[1] = Wlo + (size_t)n0*Kp;

    int NC = Kp >> 6;                       // 64-wide chunks
    int lrow = tid>>3, lseg = tid&7;

    {   // prologue: chunk 0 -> stage 0
        #pragma unroll
        for (int v=0;v<2;v++){
            #pragma unroll
            for (int i=0;i<4;i++){
                int row = lrow + i*32;
                cpasync16(smaddr(&sm[v*TSZA + row*SST2 + lseg*8]),
                          gA[v] + (size_t)row*Kp + lseg*8);
            }
            #pragma unroll
            for (int i=0;i<8;i++){
                int row = lrow + i*32;
                cpasync16(smaddr(&sm[2*TSZA + v*TSZW + row*SST2 + lseg*8]),
                          gW[v] + (size_t)row*Kp + lseg*8);
            }
        }
        asm volatile("cp.async.commit_group;" ::: "memory");
    }

    int ar = lane & 15;
    int ac = (lane >> 4) * 8;
    int brn = (lane & 7) + ((lane & 16) ? 8 : 0);
    int bc  = (lane & 8) ? 8 : 0;

    for (int c=0;c<NC;c++){
        if (c+1 < NC){
            int k0 = (c+1)*64, s = (c+1)&1;
            #pragma unroll
            for (int v=0;v<2;v++){
                #pragma unroll
                for (int i=0;i<4;i++){
                    int row = lrow + i*32;
                    cpasync16(smaddr(&sm[s*STGH + v*TSZA + row*SST2 + lseg*8]),
                              gA[v] + (size_t)row*Kp + k0 + lseg*8);
                }
                #pragma unroll
                for (int i=0;i<8;i++){
                    int row = lrow + i*32;
                    cpasync16(smaddr(&sm[s*STGH + 2*TSZA + v*TSZW + row*SST2 + lseg*8]),
                              gW[v] + (size_t)row*Kp + k0 + lseg*8);
                }
            }
            asm volatile("cp.async.commit_group;" ::: "memory");
            asm volatile("cp.async.wait_group 1;" ::: "memory");
        } else {
            asm volatile("cp.async.wait_group 0;" ::: "memory");
        }
        __syncthreads();
        int s = c & 1;
        const __nv_bfloat16* tA_hi = sm + s*STGH;
        const __nv_bfloat16* tA_lo = sm + s*STGH + TSZA;
        const __nv_bfloat16* tW_hi = sm + s*STGH + 2*TSZA;
        const __nv_bfloat16* tW_lo = sm + s*STGH + 2*TSZA + TSZW;

        #pragma unroll
        for (int ks=0; ks<4; ks++){
            int ko = ks*16;
            u32 Af[4][4], Whf[4][4], Wlf[4][4];
            #pragma unroll
            for (int mi=0;mi<4;mi++)
                ldsm4(Af[mi], smaddr(&tA_hi[(wm + mi*16 + ar)*SST2 + ko + ac]));
            #pragma unroll
            for (int g=0;g<4;g++)
                ldsm4(Whf[g], smaddr(&tW_hi[(wn + g*16 + brn)*SST2 + ko + bc]));
            // pass 1: Ahi * Whi
            #pragma unroll
            for (int mi=0;mi<4;mi++)
                #pragma unroll
                for (int ni=0;ni<8;ni++)
                    mma16816(acc[mi][ni], Af[mi], Whf[ni>>1][(ni&1)*2], Whf[ni>>1][(ni&1)*2+1]);
            // pass 2: Ahi * Wlo
            #pragma unroll
            for (int g=0;g<4;g++)
                ldsm4(Wlf[g], smaddr(&tW_lo[(wn + g*16 + brn)*SST2 + ko + bc]));
            #pragma unroll
            for (int mi=0;mi<4;mi++)
                #pragma unroll
                for (int ni=0;ni<8;ni++)
                    mma16816(acc[mi][ni], Af[mi], Wlf[ni>>1][(ni&1)*2], Wlf[ni>>1][(ni&1)*2+1]);
            // pass 3: Alo * Whi
            #pragma unroll
            for (int mi=0;mi<4;mi++)
                ldsm4(Af[mi], smaddr(&tA_lo[(wm + mi*16 + ar)*SST2 + ko + ac]));
            #pragma unroll
            for (int mi=0;mi<4;mi++)
                #pragma unroll
                for (int ni=0;ni<8;ni++)
                    mma16816(acc[mi][ni], Af[mi], Whf[ni>>1][(ni&1)*2], Whf[ni>>1][(ni&1)*2+1]);
        }
        __syncthreads();
    }

    // epilogue
    int er = lane>>2, ec = (lane&3)*2;
    #pragma unroll
    for (int mi=0;mi<4;mi++){
        #pragma unroll
        for (int ni=0;ni<8;ni++){
            int gm = m0 + wm + mi*16 + er;
            int gn = n0 + wn + ni*8 + ec;
            float b0 = bias ? bias[gn]   : 0.f;
            float b1 = bias ? bias[gn+1] : 0.f;
            float v0 = acc[mi][ni][0] + b0;
            float v1 = acc[mi][ni][1] + b1;
            float v2 = acc[mi][ni][2] + b0;
            float v3 = acc[mi][ni][3] + b1;
            if (act){ v0 = tanh_(v0); v1 = tanh_(v1); v2 = tanh_(v2); v3 = tanh_(v3); }
            *(float2*)&C[(size_t)gm*N + gn]     = make_float2(v0, v1);
            *(float2*)&C[(size_t)(gm+8)*N + gn] = make_float2(v2, v3);
        }
    }
}

// ------------- fp32 GEMM (head only) -------------
__global__ __launch_bounds__(256,2)
void gemm128(const float* __restrict__ A, const float* __restrict__ B,
             const float* __restrict__ bias, float* __restrict__ C,
             int M, int N, int K, int transB, int act)
{
    __shared__ float As2[16][264];
    __shared__ float Bs[16][132];
    int row0 = blockIdx.y*128, col0 = blockIdx.x*128;
    int tid = threadIdx.x;
    int tm = tid >> 4, tn = tid & 15;
    u64 acc[8][4];
    #pragma unroll
    for (int i=0;i<8;i++)
        #pragma unroll
        for (int j=0;j<4;j++) acc[i][j] = 0ull;

    for (int k0=0;k0<K;k0+=16){
        #pragma unroll
        for (int i=0;i<8;i++){
            int idx = tid + i*256;
            int r = idx >> 4, kk = idx & 15;
            int gr = row0+r, gk = k0+kk;
            float v = (gr<M && gk<K) ? A[(size_t)gr*K + gk] : 0.f;
            *(float2*)&As2[kk][2*r] = make_float2(v, v);
        }
        if (transB){
            #pragma unroll
            for (int i=0;i<8;i++){
                int idx = tid + i*256;
                int nn = idx >> 4, kk = idx & 15;
                int gk = k0+kk, gn = col0+nn;
                Bs[kk][nn] = (gk<K && gn<N) ? B[(size_t)gn*K+gk] : 0.f;
            }
        } else {
            #pragma unroll
            for (int i=0;i<8;i++){
                int idx = tid + i*256;
                int nn = idx & 127, kk = idx >> 7;
                int gk = k0+kk, gn = col0+nn;
                Bs[kk][nn] = (gk<K && gn<N) ? B[(size_t)gk*N+gn] : 0.f;
            }
        }
        __syncthreads();
        #pragma unroll
        for (int kk=0;kk<16;kk++){
            F4 b0, b1, a0, a1, a2, a3;
            b0.v = *(const float4*)&Bs[kk][tn*8];
            b1.v = *(const float4*)&Bs[kk][tn*8+4];
            a0.v = *(const float4*)&As2[kk][tm*16];
            a1.v = *(const float4*)&As2[kk][tm*16+4];
            a2.v = *(const float4*)&As2[kk][tm*16+8];
            a3.v = *(const float4*)&As2[kk][tm*16+12];
            u64 bd[4] = { b0.d[0], b0.d[1], b1.d[0], b1.d[1] };
            u64 ad[8] = { a0.d[0], a0.d[1], a1.d[0], a1.d[1],
                          a2.d[0], a2.d[1], a3.d[0], a3.d[1] };
            #pragma unroll
            for (int i=0;i<8;i++)
                #pragma unroll
                for (int j=0;j<4;j++)
                    acc[i][j] = ffma2(ad[i], bd[j], acc[i][j]);
        }
        __syncthreads();
    }
    #pragma unroll
    for (int i=0;i<8;i++){
        int gr = row0 + tm*8 + i;
        if (gr >= M) continue;
        #pragma unroll
        for (int j=0;j<4;j++){
            float2 v = unpack2(acc[i][j]);
            int gn = col0 + tn*8 + j*2;
            if (gn < N){
                float x = v.x + (bias ? bias[gn] : 0.f);
                if (act) x = tanh_(x);
                C[(size_t)gr*N + gn] = x;
            }
            if (gn+1 < N){
                float y = v.y + (bias ? bias[gn+1] : 0.f);
                if (act) y = tanh_(y);
                C[(size_t)gr*N + gn+1] = y;
            }
        }
    }
}

// -- LSTM scan: 128 threads, 8 rows/thread, 96-row SMEM W cache + pipelined tail --
#define HS 20
#define WCACHE 96
#define SCAN_SMEM ((WCACHE*G4 + 2*128*HS)*4)   /* 217088 B */
#define ROWX ((size_t)Tt*G4)
#define ROWH ((size_t)Tt*256)

__global__ __launch_bounds__(128,1)
void scan_kernel(const float* __restrict__ xwFp, const float* __restrict__ xwBp,
                 const float* __restrict__ wTF, const float* __restrict__ wTB,
                 __nv_bfloat16* __restrict__ ahi, __nv_bfloat16* __restrict__ alo,
                 float* __restrict__ hout)
{
    extern __shared__ float smf[];
    float* Ws  = smf;                 // WCACHE x 512
    float* hsA = smf + WCACHE*G4;     // 128 x HS (dup pairs of 8 rows)
    float* hsB = hsA + 128*HS;
    int h = threadIdx.x;              // 0..127
    int dir = blockIdx.x >> 6;
    int grp = blockIdx.x & 63;
    int b0 = grp*8;
    const float* xw = dir ? xwBp : xwFp;
    const float* wD = dir ? wTB : wTF;
    int hOff = dir*128;

    for (int i=h;i<WCACHE*G4;i+=128) Ws[i] = wD[i];
    for (int i=h;i<2*128*HS;i+=128) hsA[i] = 0.f;
    float cst[8] = {0.f,0.f,0.f,0.f,0.f,0.f,0.f,0.f};

    const float* xb = xw + (size_t)b0*ROWX + 4*h;
    __nv_bfloat16* ahb = ahi + (size_t)b0*ROWH + hOff + h;
    __nv_bfloat16* alb = alo + (size_t)b0*ROWH + hOff + h;
    float* hob = hout ? (hout + (size_t)b0*ROWH + hOff + h) : (float*)0;
    __syncthreads();

    for (int s=0;s<Tt;s++){
        int t = dir ? (Tt-1-s) : s;
        float* hsR = (s&1) ? hsB : hsA;
        float* hsW = (s&1) ? hsA : hsB;

        // xv loads + first streamed W block: issued early, consumed after long compute
        F4 xv[8];
        size_t tX = (size_t)t*G4;
        #pragma unroll
        for (int r=0;r<8;r++) xv[r].v = *(const float4*)&xb[r*ROWX + tX];
        F4 wp[8];
        #pragma unroll
        for (int j=0;j<8;j++) wp[j].v = *(const float4*)&wD[(size_t)(WCACHE+j)*G4 + 4*h];

        u64 aIF[8] = {0,0,0,0,0,0,0,0}, aGO[8] = {0,0,0,0,0,0,0,0};
        // SMEM-cached W rows
        #pragma unroll 4
        for (int k=0;k<WCACHE;k++){
            F4 w;  w.v  = *(const float4*)&Ws[k*G4 + 4*h];
            F4 p0; p0.v = *(const float4*)&hsR[k*HS];
            F4 p1; p1.v = *(const float4*)&hsR[k*HS + 4];
            F4 p2; p2.v = *(const float4*)&hsR[k*HS + 8];
            F4 p3; p3.v = *(const float4*)&hsR[k*HS + 12];
            aIF[0]=ffma2(p0.d[0], w.d[0], aIF[0]); aGO[0]=ffma2(p0.d[0], w.d[1], aGO[0]);
            aIF[1]=ffma2(p0.d[1], w.d[0], aIF[1]); aGO[1]=ffma2(p0.d[1], w.d[1], aGO[1]);
            aIF[2]=ffma2(p1.d[0], w.d[0], aIF[2]); aGO[2]=ffma2(p1.d[0], w.d[1], aGO[2]);
            aIF[3]=ffma2(p1.d[1], w.d[0], aIF[3]); aGO[3]=ffma2(p1.d[1], w.d[1], aGO[3]);
            aIF[4]=ffma2(p2.d[0], w.d[0], aIF[4]); aGO[4]=ffma2(p2.d[0], w.d[1], aGO[4]);
            aIF[5]=ffma2(p2.d[1], w.d[0], aIF[5]); aGO[5]=ffma2(p2.d[1], w.d[1], aGO[5]);
            aIF[6]=ffma2(p3.d[0], w.d[0], aIF[6]); aGO[6]=ffma2(p3.d[0], w.d[1], aGO[6]);
            aIF[7]=ffma2(p3.d[1], w.d[0], aIF[7]); aGO[7]=ffma2(p3.d[1], w.d[1], aGO[7]);
        }
        // streamed tail rows (WCACHE..127), one block prefetched ahead
        #pragma unroll
        for (int kb=WCACHE;kb<128;kb+=8){
            F4 wc[8];
            #pragma unroll
            for (int j=0;j<8;j++) wc[j] = wp[j];
            if (kb+8 < 128){
                #pragma unroll
                for (int j=0;j<8;j++) wp[j].v = *(const float4*)&wD[(size_t)(kb+8+j)*G4 + 4*h];
            }
            #pragma unroll
            for (int j=0;j<8;j++){
                int k = kb+j;
                F4 p0; p0.v = *(const float4*)&hsR[k*HS];
                F4 p1; p1.v = *(const float4*)&hsR[k*HS + 4];
                F4 p2; p2.v = *(const float4*)&hsR[k*HS + 8];
                F4 p3; p3.v = *(const float4*)&hsR[k*HS + 12];
                aIF[0]=ffma2(p0.d[0], wc[j].d[0], aIF[0]); aGO[0]=ffma2(p0.d[0], wc[j].d[1], aGO[0]);
                aIF[1]=ffma2(p0.d[1], wc[j].d[0], aIF[1]); aGO[1]=ffma2(p0.d[1], wc[j].d[1], aGO[1]);
                aIF[2]=ffma2(p1.d[0], wc[j].d[0], aIF[2]); aGO[2]=ffma2(p1.d[0], wc[j].d[1], aGO[2]);
                aIF[3]=ffma2(p1.d[1], wc[j].d[0], aIF[3]); aGO[3]=ffma2(p1.d[1], wc[j].d[1], aGO[3]);
                aIF[4]=ffma2(p2.d[0], wc[j].d[0], aIF[4]); aGO[4]=ffma2(p2.d[0], wc[j].d[1], aGO[4]);
                aIF[5]=ffma2(p2.d[1], wc[j].d[0], aIF[5]); aGO[5]=ffma2(p2.d[1], wc[j].d[1], aGO[5]);
                aIF[6]=ffma2(p3.d[0], wc[j].d[0], aIF[6]); aGO[6]=ffma2(p3.d[0], wc[j].d[1], aGO[6]);
                aIF[7]=ffma2(p3.d[1], wc[j].d[0], aIF[7]); aGO[7]=ffma2(p3.d[1], wc[j].d[1], aGO[7]);
            }
        }
        size_t tH = (size_t)t*256;
        #pragma unroll
        for (int r=0;r<8;r++){
            float2 v1 = unpack2(aIF[r]);
            float2 v2 = unpack2(aGO[r]);
            float gi = v1.x + xv[r].f[0];
            float gf = v1.y + xv[r].f[1];
            float gg = v2.x + xv[r].f[2];
            float go = v2.y + xv[r].f[3];
            float cc = sigf(gf)*cst[r] + sigf(gi)*tanh_(gg);
            cst[r] = cc;
            float hn = sigf(go)*tanh_(cc);
            *(float2*)&hsW[h*HS + 2*r] = make_float2(hn, hn);
            __nv_bfloat16 hh = __float2bfloat16(hn);
            ahb[r*ROWH + tH] = hh;
            alb[r*ROWH + tH] = __float2bfloat16(hn - __bfloat162float(hh));
            if (hob) hob[r*ROWH + tH] = hn;
        }
        __syncthreads();
    }
}

// ------------- attention -------------
__global__ __launch_bounds__(256,1)
void att_kernel(const float* __restrict__ u, const float* __restrict__ h1,
                const float* __restrict__ v, float* __restrict__ att)
{
    __shared__ float sa[Tt];
    __shared__ float red[256];
    __shared__ float vs[256];
    int b = blockIdx.x, tid = threadIdx.x;
    int wd = tid>>5, ln = tid&31;
    vs[tid] = v[tid];
    __syncthreads();
    for (int t = wd; t < Tt; t += 8){
        const float* ur = u + ((size_t)b*Tt + t)*256;
        float s = 0.f;
        #pragma unroll
        for (int j=0;j<8;j++) s += ur[ln+32*j]*vs[ln+32*j];
        #pragma unroll
        for (int o=16;o;o>>=1) s += __shfl_xor_sync(0xFFFFFFFFu, s, o);
        if (ln==0) sa[t] = s;
    }
    __syncthreads();
    float m = -3.4e38f;
    for (int t=tid;t<Tt;t+=256) m = fmaxf(m, sa[t]);
    red[tid] = m; __syncthreads();
    for (int off=128; off>0; off>>=1){ if (tid<off) red[tid]=fmaxf(red[tid],red[tid+off]); __syncthreads(); }
    float mx = red[0]; __syncthreads();
    float sum = 0.f;
    for (int t=tid;t<Tt;t+=256){ float e = __expf(sa[t]-mx); sa[t]=e; sum+=e; }
    red[tid] = sum; __syncthreads();
    for (int off=128; off>0; off>>=1){ if (tid<off) red[tid]+=red[tid+off]; __syncthreads(); }
    float inv = __fdividef(1.f, red[0]);
    __syncthreads();
    float acc = 0.f;
    const float* hb = h1 + (size_t)b*Tt*256 + tid;
    #pragma unroll 4
    for (int t=0;t<Tt;t++) acc += hb[(size_t)t*256] * sa[t];
    att[b*256 + tid] = acc * inv;
}

// ------------- launch -------------
extern "C" void kernel_launch(void* const* d_in, const int* in_sizes, int n_in,
                              void* d_out, int out_size)
{
    const float* X      = (const float*)d_in[0];
    const float* wih0f  = (const float*)d_in[1];
    const float* whh0f  = (const float*)d_in[2];
    const float* bih0f  = (const float*)d_in[3];
    const float* bhh0f  = (const float*)d_in[4];
    const float* wih0b  = (const float*)d_in[5];
    const float* whh0b  = (const float*)d_in[6];
    const float* bih0b  = (const float*)d_in[7];
    const float* bhh0b  = (const float*)d_in[8];
    const float* wih1f  = (const float*)d_in[9];
    const float* whh1f  = (const float*)d_in[10];
    const float* bih1f  = (const float*)d_in[11];
    const float* bhh1f  = (const float*)d_in[12];
    const float* wih1b  = (const float*)d_in[13];
    const float* whh1b  = (const float*)d_in[14];
    const float* bih1b  = (const float*)d_in[15];
    const float* bhh1b  = (const float*)d_in[16];
    const float* attW   = (const float*)d_in[17];
    const float* attV   = (const float*)d_in[18];
    const float* headW  = (const float*)d_in[19];
    const float* headB  = (const float*)d_in[20];
    float* out = (float*)d_out;

    cudaFuncSetAttribute(scan_kernel, cudaFuncAttributeMaxDynamicSharedMemorySize, SCAN_SMEM);
    cudaFuncSetAttribute(mma_gemm,    cudaFuncAttributeMaxDynamicSharedMemorySize, MMA_SMEM);

    float *xwF, *xwB, *h1, *wT, *bsum, *att;
    __nv_bfloat16 *ahi, *alo, *whi, *wlo;
    cudaGetSymbolAddress((void**)&xwF, g_xwF);
    cudaGetSymbolAddress((void**)&xwB, g_xwB);
    cudaGetSymbolAddress((void**)&h1,  g_h1);
    cudaGetSymbolAddress((void**)&wT,  g_wT);
    cudaGetSymbolAddress((void**)&bsum,g_bsum);
    cudaGetSymbolAddress((void**)&att, g_att);
    cudaGetSymbolAddress((void**)&ahi, g_ahi);
    cudaGetSymbolAddress((void**)&alo, g_alo);
    cudaGetSymbolAddress((void**)&whi, g_whi);
    cudaGetSymbolAddress((void**)&wlo, g_wlo);

    transpose_split<<<dim3((Tt+31)/32,(KP0+31)/32,Bsz), dim3(32,8)>>>(X, ahi, alo);       // 1
    wsplit<<<(2*G4*KP0+255)/256,256>>>(wih0f, wih0b, whi+WOFF0F, wlo+WOFF0F,
                                       whi+WOFF0B, wlo+WOFF0B, Cc, KP0);                   // 2
    whh_fold<<<(4*Hh*G4 + 4*G4 + 255)/256,256>>>(whh0f, whh0b, whh1f, whh1b,
        bih0f, bhh0f, bih0b, bhh0b, bih1f, bhh1f, bih1b, bhh1b, wT, bsum);                 // 3

    dim3 g0(2, BT/128);
    mma_gemm<<<g0,256,MMA_SMEM>>>(ahi, alo, whi+WOFF0F, wlo+WOFF0F, bsum + 0*G4, xwF, BT, G4, KP0, 0); // 4 (profiled)
    mma_gemm<<<g0,256,MMA_SMEM>>>(ahi, alo, whi+WOFF0B, wlo+WOFF0B, bsum + 1*G4, xwB, BT, G4, KP0, 0);
    wsplit<<<(2*G4*256+255)/256,256>>>(wih1f, wih1b, whi+WOFF1F, wlo+WOFF1F,
                                       whi+WOFF1B, wlo+WOFF1B, 256, 256);
    conv_splitT<<<(256*256+255)/256,256>>>(attW, whi+WOFFATT, wlo+WOFFATT, 256, 256, 256);
    scan_kernel<<<128,128,SCAN_SMEM>>>(xwF, xwB, wT + 0*Hh*G4, wT + 1*Hh*G4, ahi, alo, (float*)0);

    // layer 1 (A = h0 splits written by scan0, K=256)
    mma_gemm<<<g0,256,MMA_SMEM>>>(ahi, alo, whi+WOFF1F, wlo+WOFF1F, bsum + 2*G4, xwF, BT, G4, 256, 0);
    mma_gemm<<<g0,256,MMA_SMEM>>>(ahi, alo, whi+WOFF1B, wlo+WOFF1B, bsum + 3*G4, xwB, BT, G4, 256, 0);
    scan_kernel<<<128,128,SCAN_SMEM>>>(xwF, xwB, wT + 2*Hh*G4, wT + 3*Hh*G4, ahi, alo, h1);

    // attention u = tanh(h1 @ att_W)  (A = h1 splits from scan1)
    mma_gemm<<<dim3(1, BT/128),256,MMA_SMEM>>>(ahi, alo, whi+WOFFATT, wlo+WOFFATT, (const float*)0, xwF, BT, 256, 256, 1);
    att_kernel<<<Bsz,256>>>(xwF, h1, attV, att);
    // head (fp32)
    gemm128<<<dim3((NCLS+127)/128,(Bsz+127)/128),256>>>(att, headW, headB, out, Bsz, NCLS, 256, 1, 0);
}